// round 5
// baseline (speedup 1.0000x reference)
#include <cuda_runtime.h>
#include <cuda_bf16.h>
#include <math.h>
#include <cstdint>

#define BB 32
#define SS 4096
#define DD 512

// ---------------------------------------------------------------------------
// scratch (no allocation allowed)
// ---------------------------------------------------------------------------
__device__ float g_qadd[BB * DD];          // q@W1 + b1 + b2
__device__ float g_scores[BB * SS];        // logits
__device__ float g_partial[BB * 8 * DD];   // context partials
__device__ unsigned short g_w2h[DD * DD];  // bf16 hi W2, [n][k]
__device__ signed char g_w2q[2 * DD * DD]; // s8 planes: [0]=hi*256, [1]=lo*2^17

// scales: aH*2^3 * bL*2^17 = 2^20 ; aL*2^12 * bH*2^8 = 2^20
#define INV20 (1.0f / 1048576.0f)

// ---------------------------------------------------------------------------
__device__ __forceinline__ float tanh_fast(float x) {
  float ax = fabsf(x);
  float e = __expf(-2.0f * ax);
  float r = __fdividef(1.0f - e, 1.0f + e);
  return copysignf(r, x);
}

__device__ __forceinline__ void mma_bf16(float* c, const uint32_t* a, const uint32_t* b) {
  asm volatile(
      "mma.sync.aligned.m16n8k16.row.col.f32.bf16.bf16.f32 "
      "{%0,%1,%2,%3},{%4,%5,%6,%7},{%8,%9},{%0,%1,%2,%3};"
      : "+f"(c[0]), "+f"(c[1]), "+f"(c[2]), "+f"(c[3])
      : "r"(a[0]), "r"(a[1]), "r"(a[2]), "r"(a[3]), "r"(b[0]), "r"(b[1]));
}

__device__ __forceinline__ void mma_s8(int* c, const uint32_t* a, const uint32_t* b) {
  asm volatile(
      "mma.sync.aligned.m16n8k32.row.col.s32.s8.s8.s32 "
      "{%0,%1,%2,%3},{%4,%5,%6,%7},{%8,%9},{%0,%1,%2,%3};"
      : "+r"(c[0]), "+r"(c[1]), "+r"(c[2]), "+r"(c[3])
      : "r"(a[0]), "r"(a[1]), "r"(a[2]), "r"(a[3]), "r"(b[0]), "r"(b[1]));
}

__device__ __forceinline__ void ldsm_x4(uint32_t* r, uint32_t addr) {
  asm volatile("ldmatrix.sync.aligned.m8n8.x4.shared.b16 {%0,%1,%2,%3}, [%4];"
               : "=r"(r[0]), "=r"(r[1]), "=r"(r[2]), "=r"(r[3])
               : "r"(addr));
}

__device__ __forceinline__ void cp16(uint32_t dst, const void* src) {
  asm volatile("cp.async.cg.shared.global [%0], [%1], 16;" :: "r"(dst), "l"(src));
}
#define CP_COMMIT() asm volatile("cp.async.commit_group;" ::: "memory")
#define CP_WAIT1() asm volatile("cp.async.wait_group 1;" ::: "memory")
#define CP_WAIT0() asm volatile("cp.async.wait_group 0;" ::: "memory")

__device__ __forceinline__ uint32_t smem_u32(const void* p) {
  uint32_t a;
  asm("{ .reg .u64 t; cvta.to.shared.u64 t, %1; cvt.u32.u64 %0, t; }" : "=r"(a) : "l"(p));
  return a;
}

__device__ __forceinline__ int clampq(int v) { return v > 127 ? 127 : (v < -127 ? -127 : v); }

// ---------------------------------------------------------------------------
// Kernel 0: W2[k][n] -> bf16 hi [n][k] + s8 hi/lo planes, via smem transpose
// ---------------------------------------------------------------------------
__global__ void __launch_bounds__(256) prep_w2_kernel(const float* __restrict__ W2) {
  __shared__ float tile[64][72];
  int kb = blockIdx.x * 64, nb = blockIdx.y * 64;
  int tid = threadIdx.x;
#pragma unroll
  for (int i = 0; i < 4; i++) {
    int t2 = tid + i * 256;
    int r = t2 >> 4, q = t2 & 15;
    float4 v = *(const float4*)(W2 + (size_t)(kb + r) * DD + nb + q * 4);
    *(float4*)&tile[r][q * 4] = v;
  }
  __syncthreads();
#pragma unroll
  for (int i = 0; i < 2; i++) {
    int t2 = tid + i * 256;
    int n = t2 >> 3, q = t2 & 7;
    uint32_t hb[4];
    uint32_t hq8[2] = {0, 0}, lq8[2] = {0, 0};
#pragma unroll
    for (int e = 0; e < 4; e++) {
      float a = tile[q * 8 + e * 2 + 0][n];
      float b = tile[q * 8 + e * 2 + 1][n];
      __nv_bfloat162 hh = __floats2bfloat162_rn(a, b);
      float2 hf = __bfloat1622float2(hh);
      hb[e] = *reinterpret_cast<uint32_t*>(&hh);
      int h0 = clampq(__float2int_rn(hf.x * 256.0f)) & 0xff;
      int h1 = clampq(__float2int_rn(hf.y * 256.0f)) & 0xff;
      int l0 = clampq(__float2int_rn((a - hf.x) * 131072.0f)) & 0xff;
      int l1 = clampq(__float2int_rn((b - hf.y) * 131072.0f)) & 0xff;
      int sh = (e & 1) * 16;
      hq8[e >> 1] |= ((uint32_t)h0 << sh) | ((uint32_t)h1 << (sh + 8));
      lq8[e >> 1] |= ((uint32_t)l0 << sh) | ((uint32_t)l1 << (sh + 8));
    }
    size_t off = (size_t)(nb + n) * DD + kb + q * 8;
    *(uint4*)(g_w2h + off) = make_uint4(hb[0], hb[1], hb[2], hb[3]);
    *(uint2*)(g_w2q + off) = make_uint2(hq8[0], hq8[1]);
    *(uint2*)(g_w2q + DD * DD + off) = make_uint2(lq8[0], lq8[1]);
  }
}

// ---------------------------------------------------------------------------
// Kernel 1: q_proj[b][n] = query[b]@W1 + b1 + b2
// ---------------------------------------------------------------------------
__global__ void __launch_bounds__(256) qproj_kernel(
    const float* __restrict__ query, const float* __restrict__ W1,
    const float* __restrict__ b1, const float* __restrict__ b2) {
  int b = blockIdx.x;
  __shared__ float qs[DD];
  for (int i = threadIdx.x; i < DD; i += 256) qs[i] = query[b * DD + i];
  __syncthreads();
  for (int n = threadIdx.x; n < DD; n += 256) {
    float acc = 0.f;
#pragma unroll 8
    for (int k = 0; k < DD; k++) acc = fmaf(qs[k], W1[k * DD + n], acc);
    g_qadd[b * DD + n] = acc + b1[n] + b2[n];
  }
}

// ---------------------------------------------------------------------------
// Kernel 2: score GEMM — bf16 hh term (HMMA) + int8 cross terms (IMMA k32).
// Block: 64 rows resident (bf16 hi + s8 hi/lo planes), W2 streamed cp.async.
// ---------------------------------------------------------------------------
#define A_STRIDE 1040           // bf16 row: (512+8)*2
#define AQ_STRIDE 528           // s8 row: 512+16
#define AH_OFF 0                // 66560
#define AQH_OFF 66560           // 33792
#define AQL_OFF 100352          // 33792
#define BST_OFF 134144
#define B_RSTRIDE 144           // bf16: (64+8)*2
#define BQ_RSTRIDE 80           // s8: 64+16
#define BH_SZ 18432             // 128*144
#define BQ_SZ 10240             // 128*80
#define B_STAGE 38912           // bf16 + s8hi + s8lo
#define Q_OFF 211968            // 134144 + 2*38912
#define V_OFF 214016
#define P_OFF 216064
#define SMEM_TOTAL 217088

__global__ void __launch_bounds__(256, 1) score_mma_kernel(
    const float* __restrict__ values, const float* __restrict__ Vv,
    const float* __restrict__ bv) {
  extern __shared__ char smem[];
  const uint32_t sb = smem_u32(smem);
  const int tid = threadIdx.x;
  const int wid = tid >> 5, lane = tid & 31;
  const int gid = lane >> 2, tig = lane & 3;
  const int wm = wid & 1, wn = wid >> 1;  // 2 m-warps x 4 n-warps
  const int m0 = blockIdx.x * 64;
  const int b = m0 >> 12;

  float* qsh = (float*)(smem + Q_OFF);
  float* vsh = (float*)(smem + V_OFF);
  float* part = (float*)(smem + P_OFF);

  // ---- A fill: 64 rows x 512 k -> bf16 hi + s8 hi(x8) + s8 lo(x4096) ----
  for (int task = tid; task < 4096; task += 256) {
    int r = task >> 6, g = task & 63;
    const float4* p4 = (const float4*)(values + (size_t)(m0 + r) * DD + g * 8);
    float4 x0 = p4[0], x1 = p4[1];
    float xs[8] = {x0.x, x0.y, x0.z, x0.w, x1.x, x1.y, x1.z, x1.w};
    uint32_t hb[4];
    uint32_t hq8[2] = {0, 0}, lq8[2] = {0, 0};
#pragma unroll
    for (int e = 0; e < 4; e++) {
      __nv_bfloat162 hh = __floats2bfloat162_rn(xs[2 * e], xs[2 * e + 1]);
      float2 hf = __bfloat1622float2(hh);
      hb[e] = *reinterpret_cast<uint32_t*>(&hh);
      int h0 = __float2int_rn(hf.x * 8.0f) & 0xff;
      int h1 = __float2int_rn(hf.y * 8.0f) & 0xff;
      int l0 = __float2int_rn((xs[2 * e] - hf.x) * 4096.0f) & 0xff;
      int l1 = __float2int_rn((xs[2 * e + 1] - hf.y) * 4096.0f) & 0xff;
      int sh = (e & 1) * 16;
      hq8[e >> 1] |= ((uint32_t)h0 << sh) | ((uint32_t)h1 << (sh + 8));
      lq8[e >> 1] |= ((uint32_t)l0 << sh) | ((uint32_t)l1 << (sh + 8));
    }
    *(uint4*)(smem + AH_OFF + r * A_STRIDE + g * 16) = make_uint4(hb[0], hb[1], hb[2], hb[3]);
    *(uint2*)(smem + AQH_OFF + r * AQ_STRIDE + g * 8) = make_uint2(hq8[0], hq8[1]);
    *(uint2*)(smem + AQL_OFF + r * AQ_STRIDE + g * 8) = make_uint2(lq8[0], lq8[1]);
  }
  for (int i = tid; i < DD; i += 256) {
    qsh[i] = g_qadd[b * DD + i];
    vsh[i] = Vv[i];
  }

  // ldmatrix per-lane addresses
  const int a_row = ((lane >> 3) & 1) * 8 + (lane & 7);
  const int a_colB = (lane >> 4) * 16;  // byte offset within row
  const uint32_t aH_addr = sb + AH_OFF + (wm * 32 + a_row) * A_STRIDE + a_colB;
  const uint32_t aQh_addr = sb + AQH_OFF + (wm * 32 + a_row) * AQ_STRIDE + a_colB;
  const uint32_t aQl_addr = aQh_addr + (AQL_OFF - AQH_OFF);
  const int b_row = ((lane >> 4) & 1) * 8 + (lane & 7);
  const int b_colB = ((lane >> 3) & 1) * 16;
  const uint32_t b_off = (wn * 32 + b_row) * B_RSTRIDE + b_colB;
  const uint32_t bq_off = (wn * 32 + b_row) * BQ_RSTRIDE + b_colB;

  float rowsum[4] = {0.f, 0.f, 0.f, 0.f};

  for (int nc = 0; nc < 4; ++nc) {
    float acc[2][4][4];
    int accQ[2][4][4];
#pragma unroll
    for (int mi = 0; mi < 2; mi++)
#pragma unroll
      for (int ni = 0; ni < 4; ni++)
#pragma unroll
        for (int j = 0; j < 4; j++) {
          acc[mi][ni][j] = 0.f;
          accQ[mi][ni][j] = 0;
        }

    const unsigned short* Bh = g_w2h + (size_t)(nc * 128) * DD;
    const signed char* Bq = g_w2q + (size_t)(nc * 128) * DD;

    // issue stage 0 (kt=0)
    {
      uint32_t st = sb + BST_OFF;
#pragma unroll
      for (int i = 0; i < 4; i++) {
        int t2 = tid + i * 256;
        int r = t2 >> 3, q = t2 & 7;
        cp16(st + r * B_RSTRIDE + q * 16, Bh + (size_t)r * DD + q * 8);
      }
#pragma unroll
      for (int i = 0; i < 2; i++) {
        int t2 = tid + i * 256;
        int r = t2 >> 2, q = t2 & 3;
        const signed char* srcp = Bq + (size_t)r * DD + q * 16;
        cp16(st + BH_SZ + r * BQ_RSTRIDE + q * 16, srcp);
        cp16(st + BH_SZ + BQ_SZ + r * BQ_RSTRIDE + q * 16, srcp + DD * DD);
      }
      CP_COMMIT();
    }

    for (int kt = 0; kt < 8; ++kt) {
      if (kt < 7) {
        uint32_t st = sb + BST_OFF + ((kt + 1) & 1) * B_STAGE;
        int kb2 = (kt + 1) * 64;
#pragma unroll
        for (int i = 0; i < 4; i++) {
          int t2 = tid + i * 256;
          int r = t2 >> 3, q = t2 & 7;
          cp16(st + r * B_RSTRIDE + q * 16, Bh + (size_t)r * DD + kb2 + q * 8);
        }
#pragma unroll
        for (int i = 0; i < 2; i++) {
          int t2 = tid + i * 256;
          int r = t2 >> 2, q = t2 & 3;
          const signed char* srcp = Bq + (size_t)r * DD + kb2 + q * 16;
          cp16(st + BH_SZ + r * BQ_RSTRIDE + q * 16, srcp);
          cp16(st + BH_SZ + BQ_SZ + r * BQ_RSTRIDE + q * 16, srcp + DD * DD);
        }
        CP_COMMIT();
        CP_WAIT1();
      } else {
        CP_WAIT0();
      }
      __syncthreads();  // stage kt ready (and A ready on first pass)

      const uint32_t stage = sb + BST_OFF + (kt & 1) * B_STAGE;
#pragma unroll
      for (int s = 0; s < 2; ++s) {  // two k32 steps per kt
        const int kg = kt * 64 + s * 32;  // k element index
        uint32_t aH[2][2][4], aQl[2][4], aQh[2][4];
        ldsm_x4(aH[0][0], aH_addr + kg * 2);
        ldsm_x4(aH[0][1], aH_addr + kg * 2 + 32);
        ldsm_x4(aH[1][0], aH_addr + 16 * A_STRIDE + kg * 2);
        ldsm_x4(aH[1][1], aH_addr + 16 * A_STRIDE + kg * 2 + 32);
        ldsm_x4(aQl[0], aQl_addr + kg);
        ldsm_x4(aQl[1], aQl_addr + 16 * AQ_STRIDE + kg);
        ldsm_x4(aQh[0], aQh_addr + kg);
        ldsm_x4(aQh[1], aQh_addr + 16 * AQ_STRIDE + kg);
        uint32_t bH[2][2][4], bQh[2][4], bQl[2][4];
        uint32_t bb = stage + b_off + s * 64;
        ldsm_x4(bH[0][0], bb);
        ldsm_x4(bH[0][1], bb + 16 * B_RSTRIDE);
        ldsm_x4(bH[1][0], bb + 32);
        ldsm_x4(bH[1][1], bb + 32 + 16 * B_RSTRIDE);
        uint32_t qb = stage + BH_SZ + bq_off + s * 32;
        ldsm_x4(bQh[0], qb);
        ldsm_x4(bQh[1], qb + 16 * BQ_RSTRIDE);
        ldsm_x4(bQl[0], qb + BQ_SZ);
        ldsm_x4(bQl[1], qb + BQ_SZ + 16 * BQ_RSTRIDE);
#pragma unroll
        for (int mi = 0; mi < 2; mi++)
#pragma unroll
          for (int ni = 0; ni < 4; ni++) {
            const int g2 = ni >> 1, h2 = (ni & 1) * 2;
            mma_bf16(acc[mi][ni], aH[mi][0], &bH[0][g2][h2]);
            mma_bf16(acc[mi][ni], aH[mi][1], &bH[1][g2][h2]);
            mma_s8(accQ[mi][ni], aQl[mi], &bQh[g2][h2]);
            mma_s8(accQ[mi][ni], aQh[mi], &bQl[g2][h2]);
          }
      }
      __syncthreads();  // all readers done before stage overwrite
    }

    // epilogue for this 128-col chunk
#pragma unroll
    for (int mi = 0; mi < 2; mi++)
#pragma unroll
      for (int ni = 0; ni < 4; ni++)
#pragma unroll
        for (int j = 0; j < 4; j++) {
          int n = nc * 128 + wn * 32 + ni * 8 + tig * 2 + (j & 1);
          float v = acc[mi][ni][j] + (float)accQ[mi][ni][j] * INV20;
          float h = tanh_fast(v + qsh[n]);
          rowsum[mi * 2 + (j >> 1)] = fmaf(h, vsh[n], rowsum[mi * 2 + (j >> 1)]);
        }
  }

#pragma unroll
  for (int i = 0; i < 4; i++) {
    rowsum[i] += __shfl_xor_sync(0xffffffffu, rowsum[i], 1);
    rowsum[i] += __shfl_xor_sync(0xffffffffu, rowsum[i], 2);
  }
  if (tig == 0) {
#pragma unroll
    for (int mi = 0; mi < 2; mi++)
#pragma unroll
      for (int ri = 0; ri < 2; ri++) {
        int row = wm * 32 + mi * 16 + ri * 8 + gid;
        part[wn * 64 + row] = rowsum[mi * 2 + ri];
      }
  }
  __syncthreads();
  if (tid < 64) {
    float s = part[tid] + part[64 + tid] + part[128 + tid] + part[192 + tid];
    g_scores[m0 + tid] = s + bv[0];
  }
}

// ---------------------------------------------------------------------------
// Kernel 3: softmax over S per batch, attn -> d_out[B*D ..]
// ---------------------------------------------------------------------------
__global__ void __launch_bounds__(256) softmax_kernel(float* __restrict__ out) {
  int b = blockIdx.x;
  const float* sc = g_scores + b * SS;
  float* attn = out + BB * DD + (size_t)b * SS;
  __shared__ float redm[8];
  __shared__ float reds[8];
  __shared__ float bm, bs;
  int tid = threadIdx.x, lane = tid & 31, w = tid >> 5;

  float m = -1e30f;
  for (int i = tid; i < SS; i += 256) m = fmaxf(m, sc[i]);
#pragma unroll
  for (int o = 16; o; o >>= 1) m = fmaxf(m, __shfl_xor_sync(0xffffffffu, m, o));
  if (lane == 0) redm[w] = m;
  __syncthreads();
  if (tid == 0) {
    float v = redm[0];
#pragma unroll
    for (int i = 1; i < 8; i++) v = fmaxf(v, redm[i]);
    bm = v;
  }
  __syncthreads();
  m = bm;

  float sum = 0.f;
  for (int i = tid; i < SS; i += 256) sum += expf(sc[i] - m);
#pragma unroll
  for (int o = 16; o; o >>= 1) sum += __shfl_xor_sync(0xffffffffu, sum, o);
  if (lane == 0) reds[w] = sum;
  __syncthreads();
  if (tid == 0) {
    float v = 0.f;
#pragma unroll
    for (int i = 0; i < 8; i++) v += reds[i];
    bs = v;
  }
  __syncthreads();
  float inv = 1.0f / bs;
  for (int i = tid; i < SS; i += 256) attn[i] = expf(sc[i] - m) * inv;
}

// ---------------------------------------------------------------------------
// Kernel 4/5: context = sum_s attn * values (deterministic two-stage)
// ---------------------------------------------------------------------------
__global__ void __launch_bounds__(128) ctx_partial_kernel(
    const float* __restrict__ values, const float* __restrict__ out) {
  int d = blockIdx.x * 128 + threadIdx.x;
  int scnk = blockIdx.y;
  int b = blockIdx.z;
  const float* attn = out + BB * DD + (size_t)b * SS + scnk * (SS / 8);
  const float* vb = values + ((size_t)b * SS + (size_t)scnk * (SS / 8)) * DD + d;
  float acc = 0.f;
  for (int s = 0; s < SS / 8; s += 8) {
#pragma unroll
    for (int u = 0; u < 8; u++)
      acc = fmaf(attn[s + u], vb[(size_t)(s + u) * DD], acc);
  }
  g_partial[((b * 8) + scnk) * DD + d] = acc;
}

__global__ void __launch_bounds__(256) ctx_reduce_kernel(float* __restrict__ out) {
  int idx = blockIdx.x * 256 + threadIdx.x;
  if (idx >= BB * DD) return;
  int b = idx >> 9;
  int d = idx & 511;
  float acc = 0.f;
#pragma unroll
  for (int p = 0; p < 8; p++) acc += g_partial[(b * 8 + p) * DD + d];
  out[idx] = acc;
}

// ---------------------------------------------------------------------------
extern "C" void kernel_launch(void* const* d_in, const int* in_sizes, int n_in,
                              void* d_out, int out_size) {
  const float* query = (const float*)d_in[0];
  const float* values = (const float*)d_in[1];
  const float* W1 = (const float*)d_in[2];
  const float* b1 = (const float*)d_in[3];
  const float* W2 = (const float*)d_in[4];
  const float* b2 = (const float*)d_in[5];
  const float* Vv = (const float*)d_in[6];
  const float* bv = (const float*)d_in[7];
  float* out = (float*)d_out;

  cudaFuncSetAttribute(score_mma_kernel,
                       cudaFuncAttributeMaxDynamicSharedMemorySize, SMEM_TOTAL);

  prep_w2_kernel<<<dim3(8, 8), 256>>>(W2);
  qproj_kernel<<<BB, 256>>>(query, W1, b1, b2);
  score_mma_kernel<<<(BB * SS) / 64, 256, SMEM_TOTAL>>>(values, Vv, bv);
  softmax_kernel<<<BB, 256>>>(out);
  ctx_partial_kernel<<<dim3(DD / 128, 8, BB), 128>>>(values, out);
  ctx_reduce_kernel<<<(BB * DD + 255) / 256, 256>>>(out);
}

// round 6
// speedup vs baseline: 2.2264x; 2.2264x over previous
#include <cuda_runtime.h>
#include <cuda_fp16.h>
#include <math.h>
#include <cstdint>

#define BB 32
#define SS 4096
#define DD 512

// ---------------------------------------------------------------------------
// scratch (no allocation allowed)
// ---------------------------------------------------------------------------
__device__ float g_qadd[BB * DD];          // q@W1 + b1 + b2
__device__ float g_scores[BB * SS];        // logits
__device__ float g_partial[BB * 8 * DD];   // context partials
__device__ unsigned short g_w2f[2 * DD * DD];  // fp16 hi/lo W2, [n][k] k-contiguous

// ---------------------------------------------------------------------------
__device__ __forceinline__ float tanh_fast(float x) {
  float ax = fabsf(x);
  float e = __expf(-2.0f * ax);
  float r = __fdividef(1.0f - e, 1.0f + e);
  return copysignf(r, x);
}

// fp16 split: x = hi + lo, hi/lo fp16
__device__ __forceinline__ void split2h(float a, float b, uint32_t& h, uint32_t& l) {
  __half2 hh = __floats2half2_rn(a, b);
  float2 hf = __half22float2(hh);
  __half2 ll = __floats2half2_rn(a - hf.x, b - hf.y);
  h = *reinterpret_cast<uint32_t*>(&hh);
  l = *reinterpret_cast<uint32_t*>(&ll);
}

__device__ __forceinline__ void mma_f16(float* c, const uint32_t* a, const uint32_t* b) {
  asm volatile(
      "mma.sync.aligned.m16n8k16.row.col.f32.f16.f16.f32 "
      "{%0,%1,%2,%3},{%4,%5,%6,%7},{%8,%9},{%0,%1,%2,%3};"
      : "+f"(c[0]), "+f"(c[1]), "+f"(c[2]), "+f"(c[3])
      : "r"(a[0]), "r"(a[1]), "r"(a[2]), "r"(a[3]), "r"(b[0]), "r"(b[1]));
}

__device__ __forceinline__ void ldsm_x4(uint32_t* r, uint32_t addr) {
  asm volatile("ldmatrix.sync.aligned.m8n8.x4.shared.b16 {%0,%1,%2,%3}, [%4];"
               : "=r"(r[0]), "=r"(r[1]), "=r"(r[2]), "=r"(r[3])
               : "r"(addr));
}

__device__ __forceinline__ void cp16(uint32_t dst, const void* src) {
  asm volatile("cp.async.cg.shared.global [%0], [%1], 16;" :: "r"(dst), "l"(src));
}
#define CP_COMMIT() asm volatile("cp.async.commit_group;" ::: "memory")
#define CP_WAIT1() asm volatile("cp.async.wait_group 1;" ::: "memory")
#define CP_WAIT0() asm volatile("cp.async.wait_group 0;" ::: "memory")

__device__ __forceinline__ uint32_t smem_u32(const void* p) {
  uint32_t a;
  asm("{ .reg .u64 t; cvta.to.shared.u64 t, %1; cvt.u32.u64 %0, t; }" : "=r"(a) : "l"(p));
  return a;
}

// ---------------------------------------------------------------------------
// Kernel 0: W2[k][n] -> fp16 hi/lo transposed to [n][k], via smem tile
// ---------------------------------------------------------------------------
__global__ void __launch_bounds__(256) prep_w2_kernel(const float* __restrict__ W2) {
  __shared__ float tile[64][72];
  int kb = blockIdx.x * 64, nb = blockIdx.y * 64;
  int tid = threadIdx.x;
#pragma unroll
  for (int i = 0; i < 4; i++) {
    int t2 = tid + i * 256;             // 1024 = 64 krows * 16 float4
    int r = t2 >> 4, q = t2 & 15;
    float4 v = *(const float4*)(W2 + (size_t)(kb + r) * DD + nb + q * 4);
    *(float4*)&tile[r][q * 4] = v;
  }
  __syncthreads();
#pragma unroll
  for (int i = 0; i < 2; i++) {
    int t2 = tid + i * 256;             // 512 = 64 nrows * 8 uint4
    int n = t2 >> 3, q = t2 & 7;
    uint32_t h[4], l[4];
#pragma unroll
    for (int e = 0; e < 4; e++) {
      float a = tile[q * 8 + e * 2 + 0][n];
      float b = tile[q * 8 + e * 2 + 1][n];
      split2h(a, b, h[e], l[e]);
    }
    size_t off = (size_t)(nb + n) * DD + kb + q * 8;
    *(uint4*)(g_w2f + off) = make_uint4(h[0], h[1], h[2], h[3]);
    *(uint4*)(g_w2f + DD * DD + off) = make_uint4(l[0], l[1], l[2], l[3]);
  }
}

// ---------------------------------------------------------------------------
// Kernel 1: q_proj[b][n] = query[b]@W1 + b1 + b2
// ---------------------------------------------------------------------------
__global__ void __launch_bounds__(256) qproj_kernel(
    const float* __restrict__ query, const float* __restrict__ W1,
    const float* __restrict__ b1, const float* __restrict__ b2) {
  int b = blockIdx.x;
  __shared__ float qs[DD];
  for (int i = threadIdx.x; i < DD; i += 256) qs[i] = query[b * DD + i];
  __syncthreads();
  for (int n = threadIdx.x; n < DD; n += 256) {
    float acc = 0.f;
#pragma unroll 8
    for (int k = 0; k < DD; k++) acc = fmaf(qs[k], W1[k * DD + n], acc);
    g_qadd[b * DD + n] = acc + b1[n] + b2[n];
  }
}

// ---------------------------------------------------------------------------
// Kernel 2: score GEMM — fp16 2-term (A single fp16, W2 split hi+lo).
// ldmatrix + mma.sync, warp tile 32x32, block tile 64 rows x 128 cols/chunk,
// A resident, W2 streamed via cp.async double buffer.
// ---------------------------------------------------------------------------
#define A_STRIDE 1040          // (512+8) fp16 * 2 bytes; banks 4r mod 32
#define AH_OFF 0               // 64*1040 = 66560
#define BST_OFF 66560
#define B_RSTRIDE 144          // (64+8) fp16 * 2 bytes
#define B_PLANE 18432          // 128 rows * 144
#define B_STAGE 36864          // hi + lo
#define Q_OFF 140288           // 66560 + 2*36864
#define V_OFF 142336
#define P_OFF 144384
#define SMEM_TOTAL 145408

__global__ void __launch_bounds__(256, 1) score_mma_kernel(
    const float* __restrict__ values, const float* __restrict__ Vv,
    const float* __restrict__ bv) {
  extern __shared__ char smem[];
  const uint32_t sb = smem_u32(smem);
  const int tid = threadIdx.x;
  const int wid = tid >> 5, lane = tid & 31;
  const int gid = lane >> 2, tig = lane & 3;
  const int wm = wid & 1, wn = wid >> 1;  // 2 m-warps x 4 n-warps
  const int m0 = blockIdx.x * 64;
  const int b = m0 >> 12;

  float* qsh = (float*)(smem + Q_OFF);
  float* vsh = (float*)(smem + V_OFF);
  float* part = (float*)(smem + P_OFF);

  // ---- A fill: 64 rows x 512 k -> single fp16 plane ----
  for (int task = tid; task < 4096; task += 256) {
    int r = task >> 6, g = task & 63;
    const float4* p4 = (const float4*)(values + (size_t)(m0 + r) * DD + g * 8);
    float4 x0 = p4[0], x1 = p4[1];
    __half2 h0 = __floats2half2_rn(x0.x, x0.y);
    __half2 h1 = __floats2half2_rn(x0.z, x0.w);
    __half2 h2 = __floats2half2_rn(x1.x, x1.y);
    __half2 h3 = __floats2half2_rn(x1.z, x1.w);
    *(uint4*)(smem + AH_OFF + r * A_STRIDE + g * 16) =
        make_uint4(*(uint32_t*)&h0, *(uint32_t*)&h1, *(uint32_t*)&h2, *(uint32_t*)&h3);
  }
  for (int i = tid; i < DD; i += 256) {
    qsh[i] = g_qadd[b * DD + i];
    vsh[i] = Vv[i];
  }

  // ldmatrix per-lane addresses
  const int a_row = ((lane >> 3) & 1) * 8 + (lane & 7);
  const int a_col = (lane >> 4) * 16;
  const uint32_t aH_addr = sb + AH_OFF + (wm * 32 + a_row) * A_STRIDE + a_col;
  const int b_row = ((lane >> 4) & 1) * 8 + (lane & 7);
  const int b_col = ((lane >> 3) & 1) * 16;
  const uint32_t b_off = (wn * 32 + b_row) * B_RSTRIDE + b_col;

  float rowsum[4] = {0.f, 0.f, 0.f, 0.f};

  for (int nc = 0; nc < 4; ++nc) {
    float acc[2][4][4];
#pragma unroll
    for (int mi = 0; mi < 2; mi++)
#pragma unroll
      for (int ni = 0; ni < 4; ni++)
#pragma unroll
        for (int j = 0; j < 4; j++) acc[mi][ni][j] = 0.f;

    const unsigned short* Bg = g_w2f + (size_t)(nc * 128) * DD;

    // issue stage 0 (kt=0): 128 rows x 64 k x {hi,lo}
    {
      uint32_t st = sb + BST_OFF;
#pragma unroll
      for (int i = 0; i < 4; i++) {
        int t2 = tid + i * 256;
        int r = t2 >> 3, q = t2 & 7;
        const unsigned short* src = Bg + (size_t)r * DD + q * 8;
        uint32_t dst = st + r * B_RSTRIDE + q * 16;
        cp16(dst, src);
        cp16(dst + B_PLANE, src + DD * DD);
      }
      CP_COMMIT();
    }

    for (int kt = 0; kt < 8; ++kt) {
      if (kt < 7) {
        uint32_t st = sb + BST_OFF + ((kt + 1) & 1) * B_STAGE;
        const unsigned short* Bk = Bg + (kt + 1) * 64;
#pragma unroll
        for (int i = 0; i < 4; i++) {
          int t2 = tid + i * 256;
          int r = t2 >> 3, q = t2 & 7;
          const unsigned short* src = Bk + (size_t)r * DD + q * 8;
          uint32_t dst = st + r * B_RSTRIDE + q * 16;
          cp16(dst, src);
          cp16(dst + B_PLANE, src + DD * DD);
        }
        CP_COMMIT();
        CP_WAIT1();
      } else {
        CP_WAIT0();
      }
      __syncthreads();  // stage kt ready (and A ready on first pass)

      const uint32_t stage = sb + BST_OFF + (kt & 1) * B_STAGE;
#pragma unroll
      for (int k16 = 0; k16 < 4; ++k16) {
        int kg = kt * 64 + k16 * 16;
        uint32_t aH[2][4], bH[2][4], bL[2][4];
        ldsm_x4(aH[0], aH_addr + kg * 2);
        ldsm_x4(aH[1], aH_addr + 16 * A_STRIDE + kg * 2);
        uint32_t bbase = stage + b_off + k16 * 32;
        ldsm_x4(bH[0], bbase);
        ldsm_x4(bH[1], bbase + 16 * B_RSTRIDE);
        ldsm_x4(bL[0], bbase + B_PLANE);
        ldsm_x4(bL[1], bbase + B_PLANE + 16 * B_RSTRIDE);
#pragma unroll
        for (int mi = 0; mi < 2; mi++)
#pragma unroll
          for (int ni = 0; ni < 4; ni++) {
            const uint32_t* bh = &bH[ni >> 1][(ni & 1) * 2];
            const uint32_t* bl = &bL[ni >> 1][(ni & 1) * 2];
            mma_f16(acc[mi][ni], aH[mi], bh);
            mma_f16(acc[mi][ni], aH[mi], bl);
          }
      }
      __syncthreads();  // all readers done before stage is overwritten
    }

    // epilogue for this 128-col chunk
#pragma unroll
    for (int mi = 0; mi < 2; mi++)
#pragma unroll
      for (int ni = 0; ni < 4; ni++)
#pragma unroll
        for (int j = 0; j < 4; j++) {
          int n = nc * 128 + wn * 32 + ni * 8 + tig * 2 + (j & 1);
          float h = tanh_fast(acc[mi][ni][j] + qsh[n]);
          rowsum[mi * 2 + (j >> 1)] = fmaf(h, vsh[n], rowsum[mi * 2 + (j >> 1)]);
        }
  }

#pragma unroll
  for (int i = 0; i < 4; i++) {
    rowsum[i] += __shfl_xor_sync(0xffffffffu, rowsum[i], 1);
    rowsum[i] += __shfl_xor_sync(0xffffffffu, rowsum[i], 2);
  }
  if (tig == 0) {
#pragma unroll
    for (int mi = 0; mi < 2; mi++)
#pragma unroll
      for (int ri = 0; ri < 2; ri++) {
        int row = wm * 32 + mi * 16 + ri * 8 + gid;
        part[wn * 64 + row] = rowsum[mi * 2 + ri];
      }
  }
  __syncthreads();
  if (tid < 64) {
    float s = part[tid] + part[64 + tid] + part[128 + tid] + part[192 + tid];
    g_scores[m0 + tid] = s + bv[0];
  }
}

// ---------------------------------------------------------------------------
// Kernel 3: softmax over S per batch, attn -> d_out[B*D ..]
// ---------------------------------------------------------------------------
__global__ void __launch_bounds__(256) softmax_kernel(float* __restrict__ out) {
  int b = blockIdx.x;
  const float* sc = g_scores + b * SS;
  float* attn = out + BB * DD + (size_t)b * SS;
  __shared__ float redm[8];
  __shared__ float reds[8];
  __shared__ float bm, bs;
  int tid = threadIdx.x, lane = tid & 31, w = tid >> 5;

  float m = -1e30f;
  for (int i = tid; i < SS; i += 256) m = fmaxf(m, sc[i]);
#pragma unroll
  for (int o = 16; o; o >>= 1) m = fmaxf(m, __shfl_xor_sync(0xffffffffu, m, o));
  if (lane == 0) redm[w] = m;
  __syncthreads();
  if (tid == 0) {
    float v = redm[0];
#pragma unroll
    for (int i = 1; i < 8; i++) v = fmaxf(v, redm[i]);
    bm = v;
  }
  __syncthreads();
  m = bm;

  float sum = 0.f;
  for (int i = tid; i < SS; i += 256) sum += expf(sc[i] - m);
#pragma unroll
  for (int o = 16; o; o >>= 1) sum += __shfl_xor_sync(0xffffffffu, sum, o);
  if (lane == 0) reds[w] = sum;
  __syncthreads();
  if (tid == 0) {
    float v = 0.f;
#pragma unroll
    for (int i = 0; i < 8; i++) v += reds[i];
    bs = v;
  }
  __syncthreads();
  float inv = 1.0f / bs;
  for (int i = tid; i < SS; i += 256) attn[i] = expf(sc[i] - m) * inv;
}

// ---------------------------------------------------------------------------
// Kernel 4/5: context = sum_s attn * values (deterministic two-stage)
// ---------------------------------------------------------------------------
__global__ void __launch_bounds__(128) ctx_partial_kernel(
    const float* __restrict__ values, const float* __restrict__ out) {
  int d = blockIdx.x * 128 + threadIdx.x;
  int scnk = blockIdx.y;
  int b = blockIdx.z;
  const float* attn = out + BB * DD + (size_t)b * SS + scnk * (SS / 8);
  const float* vb = values + ((size_t)b * SS + (size_t)scnk * (SS / 8)) * DD + d;
  float acc = 0.f;
  for (int s = 0; s < SS / 8; s += 8) {
#pragma unroll
    for (int u = 0; u < 8; u++)
      acc = fmaf(attn[s + u], vb[(size_t)(s + u) * DD], acc);
  }
  g_partial[((b * 8) + scnk) * DD + d] = acc;
}

__global__ void __launch_bounds__(256) ctx_reduce_kernel(float* __restrict__ out) {
  int idx = blockIdx.x * 256 + threadIdx.x;
  if (idx >= BB * DD) return;
  int b = idx >> 9;
  int d = idx & 511;
  float acc = 0.f;
#pragma unroll
  for (int p = 0; p < 8; p++) acc += g_partial[(b * 8 + p) * DD + d];
  out[idx] = acc;
}

// ---------------------------------------------------------------------------
extern "C" void kernel_launch(void* const* d_in, const int* in_sizes, int n_in,
                              void* d_out, int out_size) {
  const float* query = (const float*)d_in[0];
  const float* values = (const float*)d_in[1];
  const float* W1 = (const float*)d_in[2];
  const float* b1 = (const float*)d_in[3];
  const float* W2 = (const float*)d_in[4];
  const float* b2 = (const float*)d_in[5];
  const float* Vv = (const float*)d_in[6];
  const float* bv = (const float*)d_in[7];
  float* out = (float*)d_out;

  cudaFuncSetAttribute(score_mma_kernel,
                       cudaFuncAttributeMaxDynamicSharedMemorySize, SMEM_TOTAL);

  prep_w2_kernel<<<dim3(8, 8), 256>>>(W2);
  qproj_kernel<<<BB, 256>>>(query, W1, b1, b2);
  score_mma_kernel<<<(BB * SS) / 64, 256, SMEM_TOTAL>>>(values, Vv, bv);
  softmax_kernel<<<BB, 256>>>(out);
  ctx_partial_kernel<<<dim3(DD / 128, 8, BB), 128>>>(values, out);
  ctx_reduce_kernel<<<(BB * DD + 255) / 256, 256>>>(out);
}

// round 7
// speedup vs baseline: 3.8741x; 1.7400x over previous
#include <cuda_runtime.h>
#include <cuda_fp16.h>
#include <math.h>
#include <cstdint>

#define BB 32
#define SS 4096
#define DD 512

// ---------------------------------------------------------------------------
// scratch (no allocation allowed)
// ---------------------------------------------------------------------------
__device__ float g_qadd[BB * DD];           // q@W1 + b1 + b2
__device__ float g_scores[BB * SS];         // logits
__device__ float g_partial[BB * 16 * DD];   // context partials
__device__ unsigned short g_w2f[DD * DD];   // fp16 W2, [n][k] k-contiguous

// ---------------------------------------------------------------------------
__device__ __forceinline__ float tanh_fast(float x) {
  float ax = fabsf(x);
  float e = __expf(-2.0f * ax);
  float r = __fdividef(1.0f - e, 1.0f + e);
  return copysignf(r, x);
}

__device__ __forceinline__ void mma_f16(float* c, const uint32_t* a, const uint32_t* b) {
  asm volatile(
      "mma.sync.aligned.m16n8k16.row.col.f32.f16.f16.f32 "
      "{%0,%1,%2,%3},{%4,%5,%6,%7},{%8,%9},{%0,%1,%2,%3};"
      : "+f"(c[0]), "+f"(c[1]), "+f"(c[2]), "+f"(c[3])
      : "r"(a[0]), "r"(a[1]), "r"(a[2]), "r"(a[3]), "r"(b[0]), "r"(b[1]));
}

__device__ __forceinline__ void ldsm_x4(uint32_t* r, uint32_t addr) {
  asm volatile("ldmatrix.sync.aligned.m8n8.x4.shared.b16 {%0,%1,%2,%3}, [%4];"
               : "=r"(r[0]), "=r"(r[1]), "=r"(r[2]), "=r"(r[3])
               : "r"(addr));
}

__device__ __forceinline__ void cp16(uint32_t dst, const void* src) {
  asm volatile("cp.async.cg.shared.global [%0], [%1], 16;" :: "r"(dst), "l"(src));
}
#define CP_COMMIT() asm volatile("cp.async.commit_group;" ::: "memory")
#define CP_WAIT1() asm volatile("cp.async.wait_group 1;" ::: "memory")
#define CP_WAIT0() asm volatile("cp.async.wait_group 0;" ::: "memory")

__device__ __forceinline__ uint32_t smem_u32(const void* p) {
  uint32_t a;
  asm("{ .reg .u64 t; cvta.to.shared.u64 t, %1; cvt.u32.u64 %0, t; }" : "=r"(a) : "l"(p));
  return a;
}

// ---------------------------------------------------------------------------
// Kernel 0: W2[k][n] -> fp16 transposed to [n][k], via smem tile
// ---------------------------------------------------------------------------
__global__ void __launch_bounds__(256) prep_w2_kernel(const float* __restrict__ W2) {
  __shared__ float tile[64][72];
  int kb = blockIdx.x * 64, nb = blockIdx.y * 64;
  int tid = threadIdx.x;
#pragma unroll
  for (int i = 0; i < 4; i++) {
    int t2 = tid + i * 256;             // 1024 = 64 krows * 16 float4
    int r = t2 >> 4, q = t2 & 15;
    float4 v = *(const float4*)(W2 + (size_t)(kb + r) * DD + nb + q * 4);
    *(float4*)&tile[r][q * 4] = v;
  }
  __syncthreads();
#pragma unroll
  for (int i = 0; i < 2; i++) {
    int t2 = tid + i * 256;             // 512 = 64 nrows * 8 uint4
    int n = t2 >> 3, q = t2 & 7;
    uint32_t h[4];
#pragma unroll
    for (int e = 0; e < 4; e++) {
      __half2 hh = __floats2half2_rn(tile[q * 8 + e * 2 + 0][n],
                                     tile[q * 8 + e * 2 + 1][n]);
      h[e] = *reinterpret_cast<uint32_t*>(&hh);
    }
    size_t off = (size_t)(nb + n) * DD + kb + q * 8;
    *(uint4*)(g_w2f + off) = make_uint4(h[0], h[1], h[2], h[3]);
  }
}

// ---------------------------------------------------------------------------
// Kernel 1: q_proj[b][n] = query[b]@W1 + b1 + b2
// ---------------------------------------------------------------------------
__global__ void __launch_bounds__(256) qproj_kernel(
    const float* __restrict__ query, const float* __restrict__ W1,
    const float* __restrict__ b1, const float* __restrict__ b2) {
  int b = blockIdx.x;
  __shared__ float qs[DD];
  for (int i = threadIdx.x; i < DD; i += 256) qs[i] = query[b * DD + i];
  __syncthreads();
  for (int n = threadIdx.x; n < DD; n += 256) {
    float acc = 0.f;
#pragma unroll 8
    for (int k = 0; k < DD; k++) acc = fmaf(qs[k], W1[k * DD + n], acc);
    g_qadd[b * DD + n] = acc + b1[n] + b2[n];
  }
}

// ---------------------------------------------------------------------------
// Kernel 2: score GEMM — single fp16 term. Block: 128 rows resident,
// warp tile 32x64 (4 m-warps x 2 n-warps), W2 streamed cp.async 2-stage.
// ---------------------------------------------------------------------------
#define A_STRIDE 1040          // (512+8) fp16 * 2 bytes
#define AH_OFF 0               // 128*1040 = 133120
#define BST_OFF 133120
#define B_RSTRIDE 144          // (64+8) fp16 * 2 bytes
#define B_STAGE 18432          // 128 rows * 144
#define Q_OFF 169984           // 133120 + 2*18432
#define V_OFF 172032
#define P_OFF 174080           // 256 floats
#define SMEM_TOTAL 175104

__global__ void __launch_bounds__(256, 1) score_mma_kernel(
    const float* __restrict__ values, const float* __restrict__ Vv,
    const float* __restrict__ bv) {
  extern __shared__ char smem[];
  const uint32_t sb = smem_u32(smem);
  const int tid = threadIdx.x;
  const int wid = tid >> 5, lane = tid & 31;
  const int gid = lane >> 2, tig = lane & 3;
  const int wm = wid & 3, wn = wid >> 2;  // 4 m-warps x 2 n-warps
  const int m0 = blockIdx.x * 128;
  const int b = m0 >> 12;

  float* qsh = (float*)(smem + Q_OFF);
  float* vsh = (float*)(smem + V_OFF);
  float* part = (float*)(smem + P_OFF);

  // ---- A fill: 128 rows x 512 k -> fp16 plane ----
  for (int task = tid; task < 8192; task += 256) {
    int r = task >> 6, g = task & 63;
    const float4* p4 = (const float4*)(values + (size_t)(m0 + r) * DD + g * 8);
    float4 x0 = p4[0], x1 = p4[1];
    __half2 h0 = __floats2half2_rn(x0.x, x0.y);
    __half2 h1 = __floats2half2_rn(x0.z, x0.w);
    __half2 h2 = __floats2half2_rn(x1.x, x1.y);
    __half2 h3 = __floats2half2_rn(x1.z, x1.w);
    *(uint4*)(smem + AH_OFF + r * A_STRIDE + g * 16) =
        make_uint4(*(uint32_t*)&h0, *(uint32_t*)&h1, *(uint32_t*)&h2, *(uint32_t*)&h3);
  }
  for (int i = tid; i < DD; i += 256) {
    qsh[i] = g_qadd[b * DD + i];
    vsh[i] = Vv[i];
  }

  // ldmatrix per-lane addresses
  const int a_row = ((lane >> 3) & 1) * 8 + (lane & 7);
  const int a_col = (lane >> 4) * 16;
  const uint32_t aH_addr = sb + AH_OFF + (wm * 32 + a_row) * A_STRIDE + a_col;
  const int b_row = ((lane >> 4) & 1) * 8 + (lane & 7);
  const int b_col = ((lane >> 3) & 1) * 16;
  const uint32_t b_off = (wn * 64 + b_row) * B_RSTRIDE + b_col;

  float rowsum[4] = {0.f, 0.f, 0.f, 0.f};

  for (int nc = 0; nc < 4; ++nc) {
    float acc[2][8][4];
#pragma unroll
    for (int mi = 0; mi < 2; mi++)
#pragma unroll
      for (int ni = 0; ni < 8; ni++)
#pragma unroll
        for (int j = 0; j < 4; j++) acc[mi][ni][j] = 0.f;

    const unsigned short* Bg = g_w2f + (size_t)(nc * 128) * DD;

    // issue stage 0 (kt=0): 128 n-rows x 64 k
    {
      uint32_t st = sb + BST_OFF;
#pragma unroll
      for (int i = 0; i < 4; i++) {
        int t2 = tid + i * 256;
        int r = t2 >> 3, q = t2 & 7;
        cp16(st + r * B_RSTRIDE + q * 16, Bg + (size_t)r * DD + q * 8);
      }
      CP_COMMIT();
    }

    for (int kt = 0; kt < 8; ++kt) {
      if (kt < 7) {
        uint32_t st = sb + BST_OFF + ((kt + 1) & 1) * B_STAGE;
        const unsigned short* Bk = Bg + (kt + 1) * 64;
#pragma unroll
        for (int i = 0; i < 4; i++) {
          int t2 = tid + i * 256;
          int r = t2 >> 3, q = t2 & 7;
          cp16(st + r * B_RSTRIDE + q * 16, Bk + (size_t)r * DD + q * 8);
        }
        CP_COMMIT();
        CP_WAIT1();
      } else {
        CP_WAIT0();
      }
      __syncthreads();  // stage kt ready (and A ready on first pass)

      const uint32_t stage = sb + BST_OFF + (kt & 1) * B_STAGE;
#pragma unroll
      for (int k16 = 0; k16 < 4; ++k16) {
        int kg = kt * 64 + k16 * 16;
        uint32_t aH[2][4], bH[4][4];
        ldsm_x4(aH[0], aH_addr + kg * 2);
        ldsm_x4(aH[1], aH_addr + 16 * A_STRIDE + kg * 2);
        uint32_t bbase = stage + b_off + k16 * 32;
        ldsm_x4(bH[0], bbase);
        ldsm_x4(bH[1], bbase + 16 * B_RSTRIDE);
        ldsm_x4(bH[2], bbase + 32 * B_RSTRIDE);
        ldsm_x4(bH[3], bbase + 48 * B_RSTRIDE);
#pragma unroll
        for (int mi = 0; mi < 2; mi++)
#pragma unroll
          for (int ni = 0; ni < 8; ni++)
            mma_f16(acc[mi][ni], aH[mi], &bH[ni >> 1][(ni & 1) * 2]);
      }
      __syncthreads();  // all readers done before stage is overwritten
    }

    // epilogue for this 128-col chunk
#pragma unroll
    for (int mi = 0; mi < 2; mi++)
#pragma unroll
      for (int ni = 0; ni < 8; ni++)
#pragma unroll
        for (int j = 0; j < 4; j++) {
          int n = nc * 128 + wn * 64 + ni * 8 + tig * 2 + (j & 1);
          float h = tanh_fast(acc[mi][ni][j] + qsh[n]);
          rowsum[mi * 2 + (j >> 1)] = fmaf(h, vsh[n], rowsum[mi * 2 + (j >> 1)]);
        }
  }

#pragma unroll
  for (int i = 0; i < 4; i++) {
    rowsum[i] += __shfl_xor_sync(0xffffffffu, rowsum[i], 1);
    rowsum[i] += __shfl_xor_sync(0xffffffffu, rowsum[i], 2);
  }
  if (tig == 0) {
#pragma unroll
    for (int mi = 0; mi < 2; mi++)
#pragma unroll
      for (int ri = 0; ri < 2; ri++) {
        int row = wm * 32 + mi * 16 + ri * 8 + gid;
        part[wn * 128 + row] = rowsum[mi * 2 + ri];
      }
  }
  __syncthreads();
  if (tid < 128) {
    g_scores[m0 + tid] = part[tid] + part[128 + tid] + bv[0];
  }
}

// ---------------------------------------------------------------------------
// Kernel 3: softmax over S per batch, attn -> d_out[B*D ..]
// ---------------------------------------------------------------------------
__global__ void __launch_bounds__(256) softmax_kernel(float* __restrict__ out) {
  int b = blockIdx.x;
  const float* sc = g_scores + b * SS;
  float* attn = out + BB * DD + (size_t)b * SS;
  __shared__ float redm[8];
  __shared__ float reds[8];
  __shared__ float bm, bs;
  int tid = threadIdx.x, lane = tid & 31, w = tid >> 5;

  float m = -1e30f;
  for (int i = tid; i < SS; i += 256) m = fmaxf(m, sc[i]);
#pragma unroll
  for (int o = 16; o; o >>= 1) m = fmaxf(m, __shfl_xor_sync(0xffffffffu, m, o));
  if (lane == 0) redm[w] = m;
  __syncthreads();
  if (tid == 0) {
    float v = redm[0];
#pragma unroll
    for (int i = 1; i < 8; i++) v = fmaxf(v, redm[i]);
    bm = v;
  }
  __syncthreads();
  m = bm;

  float sum = 0.f;
  for (int i = tid; i < SS; i += 256) sum += expf(sc[i] - m);
#pragma unroll
  for (int o = 16; o; o >>= 1) sum += __shfl_xor_sync(0xffffffffu, sum, o);
  if (lane == 0) reds[w] = sum;
  __syncthreads();
  if (tid == 0) {
    float v = 0.f;
#pragma unroll
    for (int i = 0; i < 8; i++) v += reds[i];
    bs = v;
  }
  __syncthreads();
  float inv = 1.0f / bs;
  for (int i = tid; i < SS; i += 256) attn[i] = expf(sc[i] - m) * inv;
}

// ---------------------------------------------------------------------------
// Kernel 4/5: context = sum_s attn * values (deterministic two-stage)
// ---------------------------------------------------------------------------
#define SCH 16
__global__ void __launch_bounds__(128) ctx_partial_kernel(
    const float* __restrict__ values, const float* __restrict__ out) {
  int d = blockIdx.x * 128 + threadIdx.x;
  int scnk = blockIdx.y;
  int b = blockIdx.z;
  const float* attn = out + BB * DD + (size_t)b * SS + scnk * (SS / SCH);
  const float* vb = values + ((size_t)b * SS + (size_t)scnk * (SS / SCH)) * DD + d;
  float acc = 0.f;
  for (int s = 0; s < SS / SCH; s += 8) {
#pragma unroll
    for (int u = 0; u < 8; u++)
      acc = fmaf(attn[s + u], vb[(size_t)(s + u) * DD], acc);
  }
  g_partial[((b * SCH) + scnk) * DD + d] = acc;
}

__global__ void __launch_bounds__(256) ctx_reduce_kernel(float* __restrict__ out) {
  int idx = blockIdx.x * 256 + threadIdx.x;
  if (idx >= BB * DD) return;
  int b = idx >> 9;
  int d = idx & 511;
  float acc = 0.f;
#pragma unroll
  for (int p = 0; p < SCH; p++) acc += g_partial[(b * SCH + p) * DD + d];
  out[idx] = acc;
}

// ---------------------------------------------------------------------------
extern "C" void kernel_launch(void* const* d_in, const int* in_sizes, int n_in,
                              void* d_out, int out_size) {
  const float* query = (const float*)d_in[0];
  const float* values = (const float*)d_in[1];
  const float* W1 = (const float*)d_in[2];
  const float* b1 = (const float*)d_in[3];
  const float* W2 = (const float*)d_in[4];
  const float* b2 = (const float*)d_in[5];
  const float* Vv = (const float*)d_in[6];
  const float* bv = (const float*)d_in[7];
  float* out = (float*)d_out;

  cudaFuncSetAttribute(score_mma_kernel,
                       cudaFuncAttributeMaxDynamicSharedMemorySize, SMEM_TOTAL);

  prep_w2_kernel<<<dim3(8, 8), 256>>>(W2);
  qproj_kernel<<<BB, 256>>>(query, W1, b1, b2);
  score_mma_kernel<<<(BB * SS) / 128, 256, SMEM_TOTAL>>>(values, Vv, bv);
  softmax_kernel<<<BB, 256>>>(out);
  ctx_partial_kernel<<<dim3(DD / 128, SCH, BB), 128>>>(values, out);
  ctx_reduce_kernel<<<(BB * DD + 255) / 256, 256>>>(out);
}

// round 8
// speedup vs baseline: 4.4957x; 1.1605x over previous
#include <cuda_runtime.h>
#include <cuda_fp16.h>
#include <math.h>
#include <cstdint>

#define BB 32
#define SS 4096
#define DD 512

// ---------------------------------------------------------------------------
// scratch (no allocation allowed)
// ---------------------------------------------------------------------------
__device__ float g_qadd[BB * DD];           // q@W1 + b1 + b2
__device__ float g_scores[BB * SS];         // logits
__device__ float g_partial[BB * 16 * DD];   // context partials
__device__ float g_ms[2 * BB];              // per-batch max, 1/sum
__device__ unsigned short g_w2f[DD * DD];   // fp16 W2, [n][k] k-contiguous

// ---------------------------------------------------------------------------
__device__ __forceinline__ float tanh_fast(float x) {
  float ax = fabsf(x);
  float e = __expf(-2.0f * ax);
  float r = __fdividef(1.0f - e, 1.0f + e);
  return copysignf(r, x);
}

__device__ __forceinline__ void mma_f16(float* c, const uint32_t* a, const uint32_t* b) {
  asm volatile(
      "mma.sync.aligned.m16n8k16.row.col.f32.f16.f16.f32 "
      "{%0,%1,%2,%3},{%4,%5,%6,%7},{%8,%9},{%0,%1,%2,%3};"
      : "+f"(c[0]), "+f"(c[1]), "+f"(c[2]), "+f"(c[3])
      : "r"(a[0]), "r"(a[1]), "r"(a[2]), "r"(a[3]), "r"(b[0]), "r"(b[1]));
}

__device__ __forceinline__ void ldsm_x4(uint32_t* r, uint32_t addr) {
  asm volatile("ldmatrix.sync.aligned.m8n8.x4.shared.b16 {%0,%1,%2,%3}, [%4];"
               : "=r"(r[0]), "=r"(r[1]), "=r"(r[2]), "=r"(r[3])
               : "r"(addr));
}

__device__ __forceinline__ void cp16(uint32_t dst, const void* src) {
  asm volatile("cp.async.cg.shared.global [%0], [%1], 16;" :: "r"(dst), "l"(src));
}
#define CP_COMMIT() asm volatile("cp.async.commit_group;" ::: "memory")
#define CP_WAIT1() asm volatile("cp.async.wait_group 1;" ::: "memory")
#define CP_WAIT0() asm volatile("cp.async.wait_group 0;" ::: "memory")

__device__ __forceinline__ uint32_t smem_u32(const void* p) {
  uint32_t a;
  asm("{ .reg .u64 t; cvta.to.shared.u64 t, %1; cvt.u32.u64 %0, t; }" : "=r"(a) : "l"(p));
  return a;
}

// ---------------------------------------------------------------------------
// Kernel 0: fused prep (blocks 0..63: W2 -> fp16 [n][k]) +
//           qproj (blocks 64..191: q@W1 + b1 + b2, split-k pairs)
// ---------------------------------------------------------------------------
__global__ void __launch_bounds__(256) prep_kernel(
    const float* __restrict__ W2, const float* __restrict__ query,
    const float* __restrict__ W1, const float* __restrict__ b1,
    const float* __restrict__ b2) {
  __shared__ float tile[64][72];
  __shared__ float qs[DD];
  int tid = threadIdx.x;
  if (blockIdx.x < 64) {
    int kb = (blockIdx.x & 7) * 64, nb = (blockIdx.x >> 3) * 64;
#pragma unroll
    for (int i = 0; i < 4; i++) {
      int t2 = tid + i * 256;
      int r = t2 >> 4, q = t2 & 15;
      float4 v = *(const float4*)(W2 + (size_t)(kb + r) * DD + nb + q * 4);
      *(float4*)&tile[r][q * 4] = v;
    }
    __syncthreads();
#pragma unroll
    for (int i = 0; i < 2; i++) {
      int t2 = tid + i * 256;
      int n = t2 >> 3, q = t2 & 7;
      uint32_t h[4];
#pragma unroll
      for (int e = 0; e < 4; e++) {
        __half2 hh = __floats2half2_rn(tile[q * 8 + e * 2 + 0][n],
                                       tile[q * 8 + e * 2 + 1][n]);
        h[e] = *reinterpret_cast<uint32_t*>(&hh);
      }
      size_t off = (size_t)(nb + n) * DD + kb + q * 8;
      *(uint4*)(g_w2f + off) = make_uint4(h[0], h[1], h[2], h[3]);
    }
  } else {
    int j = blockIdx.x - 64;
    int b = j >> 2, qn = j & 3;
    for (int i = tid; i < DD; i += 256) qs[i] = query[b * DD + i];
    __syncthreads();
    int n = qn * 128 + (tid >> 1);
    int k0 = (tid & 1) * 256;
    float acc = 0.f;
#pragma unroll 8
    for (int k = 0; k < 256; k++) acc = fmaf(qs[k0 + k], W1[(k0 + k) * DD + n], acc);
    acc += __shfl_xor_sync(0xffffffffu, acc, 1);
    if (!(tid & 1)) g_qadd[b * DD + n] = acc + b1[n] + b2[n];
  }
}

// ---------------------------------------------------------------------------
// Kernel 2: score GEMM — single fp16 term. Block: 128 rows resident,
// warp tile 32x64 (4 m-warps x 2 n-warps), W2 streamed cp.async 2-stage
// with 128-k stages (half the syncs).
// ---------------------------------------------------------------------------
#define A_STRIDE 1040          // (512+8) fp16 * 2 bytes
#define AH_OFF 0               // 128*1040 = 133120
#define BST_OFF 133120
#define B_RSTRIDE 272          // (128+8) fp16 * 2 bytes
#define B_STAGE 34816          // 128 rows * 272
#define Q_OFF 202752           // 133120 + 2*34816
#define V_OFF 204800
#define P_OFF 206848           // 256 floats
#define SMEM_TOTAL 207872

__global__ void __launch_bounds__(256, 1) score_mma_kernel(
    const float* __restrict__ values, const float* __restrict__ Vv,
    const float* __restrict__ bv) {
  extern __shared__ char smem[];
  const uint32_t sb = smem_u32(smem);
  const int tid = threadIdx.x;
  const int wid = tid >> 5, lane = tid & 31;
  const int gid = lane >> 2, tig = lane & 3;
  const int wm = wid & 3, wn = wid >> 2;  // 4 m-warps x 2 n-warps
  const int m0 = blockIdx.x * 128;
  const int b = m0 >> 12;

  float* qsh = (float*)(smem + Q_OFF);
  float* vsh = (float*)(smem + V_OFF);
  float* part = (float*)(smem + P_OFF);

  // ---- issue B stage0 for nc=0 first (overlaps A conversion) ----
  {
    uint32_t st = sb + BST_OFF;
#pragma unroll
    for (int i = 0; i < 8; i++) {
      int t2 = tid + i * 256;
      int r = t2 >> 4, q = t2 & 15;
      cp16(st + r * B_RSTRIDE + q * 16, g_w2f + (size_t)r * DD + q * 8);
    }
    CP_COMMIT();
  }

  // ---- A fill: 128 rows x 512 k -> fp16 plane ----
  for (int task = tid; task < 8192; task += 256) {
    int r = task >> 6, g = task & 63;
    const float4* p4 = (const float4*)(values + (size_t)(m0 + r) * DD + g * 8);
    float4 x0 = p4[0], x1 = p4[1];
    __half2 h0 = __floats2half2_rn(x0.x, x0.y);
    __half2 h1 = __floats2half2_rn(x0.z, x0.w);
    __half2 h2 = __floats2half2_rn(x1.x, x1.y);
    __half2 h3 = __floats2half2_rn(x1.z, x1.w);
    *(uint4*)(smem + AH_OFF + r * A_STRIDE + g * 16) =
        make_uint4(*(uint32_t*)&h0, *(uint32_t*)&h1, *(uint32_t*)&h2, *(uint32_t*)&h3);
  }
  for (int i = tid; i < DD; i += 256) {
    qsh[i] = g_qadd[b * DD + i];
    vsh[i] = Vv[i];
  }

  // ldmatrix per-lane addresses
  const int a_row = ((lane >> 3) & 1) * 8 + (lane & 7);
  const int a_col = (lane >> 4) * 16;
  const uint32_t aH_addr = sb + AH_OFF + (wm * 32 + a_row) * A_STRIDE + a_col;
  const int b_row = ((lane >> 4) & 1) * 8 + (lane & 7);
  const int b_col = ((lane >> 3) & 1) * 16;
  const uint32_t b_off = (wn * 64 + b_row) * B_RSTRIDE + b_col;

  float rowsum[4] = {0.f, 0.f, 0.f, 0.f};

  for (int nc = 0; nc < 4; ++nc) {
    float acc[2][8][4];
#pragma unroll
    for (int mi = 0; mi < 2; mi++)
#pragma unroll
      for (int ni = 0; ni < 8; ni++)
#pragma unroll
        for (int j = 0; j < 4; j++) acc[mi][ni][j] = 0.f;

    const unsigned short* Bg = g_w2f + (size_t)(nc * 128) * DD;

    for (int kt = 0; kt < 4; ++kt) {
      if (kt < 3) {
        uint32_t st = sb + BST_OFF + ((kt + 1) & 1) * B_STAGE;
        const unsigned short* Bk = Bg + (kt + 1) * 128;
#pragma unroll
        for (int i = 0; i < 8; i++) {
          int t2 = tid + i * 256;
          int r = t2 >> 4, q = t2 & 15;
          cp16(st + r * B_RSTRIDE + q * 16, Bk + (size_t)r * DD + q * 8);
        }
        CP_COMMIT();
        CP_WAIT1();
      } else {
        CP_WAIT0();
      }
      __syncthreads();  // stage kt ready (and A ready on first pass)

      const uint32_t stage = sb + BST_OFF + (kt & 1) * B_STAGE;
#pragma unroll
      for (int k16 = 0; k16 < 8; ++k16) {
        int kg = kt * 128 + k16 * 16;
        uint32_t aH[2][4], bH[4][4];
        ldsm_x4(aH[0], aH_addr + kg * 2);
        ldsm_x4(aH[1], aH_addr + 16 * A_STRIDE + kg * 2);
        uint32_t bbase = stage + b_off + k16 * 32;
        ldsm_x4(bH[0], bbase);
        ldsm_x4(bH[1], bbase + 16 * B_RSTRIDE);
        ldsm_x4(bH[2], bbase + 32 * B_RSTRIDE);
        ldsm_x4(bH[3], bbase + 48 * B_RSTRIDE);
#pragma unroll
        for (int mi = 0; mi < 2; mi++)
#pragma unroll
          for (int ni = 0; ni < 8; ni++)
            mma_f16(acc[mi][ni], aH[mi], &bH[ni >> 1][(ni & 1) * 2]);
      }
      __syncthreads();  // all readers done before stage is overwritten
    }

    // prefetch next nc's stage0 (both buffers free now)
    if (nc < 3) {
      uint32_t st = sb + BST_OFF;
      const unsigned short* Bn = g_w2f + (size_t)((nc + 1) * 128) * DD;
#pragma unroll
      for (int i = 0; i < 8; i++) {
        int t2 = tid + i * 256;
        int r = t2 >> 4, q = t2 & 15;
        cp16(st + r * B_RSTRIDE + q * 16, Bn + (size_t)r * DD + q * 8);
      }
      CP_COMMIT();
    }

    // epilogue for this 128-col chunk
#pragma unroll
    for (int mi = 0; mi < 2; mi++)
#pragma unroll
      for (int ni = 0; ni < 8; ni++)
#pragma unroll
        for (int j = 0; j < 4; j++) {
          int n = nc * 128 + wn * 64 + ni * 8 + tig * 2 + (j & 1);
          float h = tanh_fast(acc[mi][ni][j] + qsh[n]);
          rowsum[mi * 2 + (j >> 1)] = fmaf(h, vsh[n], rowsum[mi * 2 + (j >> 1)]);
        }
  }

#pragma unroll
  for (int i = 0; i < 4; i++) {
    rowsum[i] += __shfl_xor_sync(0xffffffffu, rowsum[i], 1);
    rowsum[i] += __shfl_xor_sync(0xffffffffu, rowsum[i], 2);
  }
  if (tig == 0) {
#pragma unroll
    for (int mi = 0; mi < 2; mi++)
#pragma unroll
      for (int ri = 0; ri < 2; ri++) {
        int row = wm * 32 + mi * 16 + ri * 8 + gid;
        part[wn * 128 + row] = rowsum[mi * 2 + ri];
      }
  }
  __syncthreads();
  if (tid < 128) {
    g_scores[m0 + tid] = part[tid] + part[128 + tid] + bv[0];
  }
}

// ---------------------------------------------------------------------------
// Kernel 3: per-batch max and 1/sum of exp
// ---------------------------------------------------------------------------
__global__ void __launch_bounds__(256) maxsum_kernel() {
  int b = blockIdx.x;
  const float* sc = g_scores + b * SS;
  __shared__ float redm[8];
  __shared__ float reds[8];
  __shared__ float bm;
  int tid = threadIdx.x, lane = tid & 31, w = tid >> 5;

  float m = -1e30f;
  for (int i = tid; i < SS; i += 256) m = fmaxf(m, sc[i]);
#pragma unroll
  for (int o = 16; o; o >>= 1) m = fmaxf(m, __shfl_xor_sync(0xffffffffu, m, o));
  if (lane == 0) redm[w] = m;
  __syncthreads();
  if (tid == 0) {
    float v = redm[0];
#pragma unroll
    for (int i = 1; i < 8; i++) v = fmaxf(v, redm[i]);
    bm = v;
  }
  __syncthreads();
  m = bm;

  float sum = 0.f;
  for (int i = tid; i < SS; i += 256) sum += expf(sc[i] - m);
#pragma unroll
  for (int o = 16; o; o >>= 1) sum += __shfl_xor_sync(0xffffffffu, sum, o);
  if (lane == 0) reds[w] = sum;
  __syncthreads();
  if (tid == 0) {
    float v = 0.f;
#pragma unroll
    for (int i = 0; i < 8; i++) v += reds[i];
    g_ms[2 * b] = m;
    g_ms[2 * b + 1] = 1.0f / v;
  }
}

// ---------------------------------------------------------------------------
// Kernel 4/5: context = sum_s attn * values, attn computed in-flight and
// written by d-chunk 0 (deterministic two-stage partials)
// ---------------------------------------------------------------------------
#define SCH 16
__global__ void __launch_bounds__(128) ctx_partial_kernel(
    const float* __restrict__ values, float* __restrict__ out) {
  int d = blockIdx.x * 128 + threadIdx.x;
  int scnk = blockIdx.y;
  int b = blockIdx.z;
  const float m = g_ms[2 * b], inv = g_ms[2 * b + 1];
  const float* sc = g_scores + (size_t)b * SS + scnk * (SS / SCH);
  float* attn = out + BB * DD + (size_t)b * SS + scnk * (SS / SCH);
  const float* vb = values + ((size_t)b * SS + (size_t)scnk * (SS / SCH)) * DD + d;
  const bool wr = (blockIdx.x == 0);
  float acc = 0.f;
  for (int s = 0; s < SS / SCH; s += 8) {
#pragma unroll
    for (int u = 0; u < 8; u++) {
      float p = expf(sc[s + u] - m) * inv;
      if (wr) attn[s + u] = p;
      acc = fmaf(p, vb[(size_t)(s + u) * DD], acc);
    }
  }
  g_partial[((b * SCH) + scnk) * DD + d] = acc;
}

__global__ void __launch_bounds__(256) ctx_reduce_kernel(float* __restrict__ out) {
  int idx = blockIdx.x * 256 + threadIdx.x;
  if (idx >= BB * DD) return;
  int b = idx >> 9;
  int d = idx & 511;
  float acc = 0.f;
#pragma unroll
  for (int p = 0; p < SCH; p++) acc += g_partial[(b * SCH + p) * DD + d];
  out[idx] = acc;
}

// ---------------------------------------------------------------------------
extern "C" void kernel_launch(void* const* d_in, const int* in_sizes, int n_in,
                              void* d_out, int out_size) {
  const float* query = (const float*)d_in[0];
  const float* values = (const float*)d_in[1];
  const float* W1 = (const float*)d_in[2];
  const float* b1 = (const float*)d_in[3];
  const float* W2 = (const float*)d_in[4];
  const float* b2 = (const float*)d_in[5];
  const float* Vv = (const float*)d_in[6];
  const float* bv = (const float*)d_in[7];
  float* out = (float*)d_out;

  cudaFuncSetAttribute(score_mma_kernel,
                       cudaFuncAttributeMaxDynamicSharedMemorySize, SMEM_TOTAL);

  prep_kernel<<<192, 256>>>(W2, query, W1, b1, b2);
  score_mma_kernel<<<(BB * SS) / 128, 256, SMEM_TOTAL>>>(values, Vv, bv);
  maxsum_kernel<<<BB, 256>>>();
  ctx_partial_kernel<<<dim3(DD / 128, SCH, BB), 128>>>(values, out);
  ctx_reduce_kernel<<<(BB * DD + 255) / 256, 256>>>(out);
}

// round 9
// speedup vs baseline: 4.7789x; 1.0630x over previous
#include <cuda_runtime.h>
#include <cuda_fp16.h>
#include <math.h>
#include <cstdint>

#define BB 32
#define SS 4096
#define DD 512

// ---------------------------------------------------------------------------
// scratch (no allocation allowed)
// ---------------------------------------------------------------------------
__device__ float g_qadd[BB * DD];           // q@W1 + b1 + b2
__device__ float g_scores[BB * SS];         // logits
__device__ float g_partial[BB * 32 * DD];   // context partials
__device__ float g_ms[2 * BB];              // per-batch max, 1/sum
__device__ unsigned short g_w2f[DD * DD];   // fp16 W2, [n][k] k-contiguous

// ---------------------------------------------------------------------------
__device__ __forceinline__ float tanh_fast(float x) {
  float r;
  asm("tanh.approx.f32 %0, %1;" : "=f"(r) : "f"(x));
  return r;
}

__device__ __forceinline__ void mma_f16(float* c, const uint32_t* a, const uint32_t* b) {
  asm volatile(
      "mma.sync.aligned.m16n8k16.row.col.f32.f16.f16.f32 "
      "{%0,%1,%2,%3},{%4,%5,%6,%7},{%8,%9},{%0,%1,%2,%3};"
      : "+f"(c[0]), "+f"(c[1]), "+f"(c[2]), "+f"(c[3])
      : "r"(a[0]), "r"(a[1]), "r"(a[2]), "r"(a[3]), "r"(b[0]), "r"(b[1]));
}

__device__ __forceinline__ void ldsm_x4(uint32_t* r, uint32_t addr) {
  asm volatile("ldmatrix.sync.aligned.m8n8.x4.shared.b16 {%0,%1,%2,%3}, [%4];"
               : "=r"(r[0]), "=r"(r[1]), "=r"(r[2]), "=r"(r[3])
               : "r"(addr));
}

__device__ __forceinline__ void cp16(uint32_t dst, const void* src) {
  asm volatile("cp.async.cg.shared.global [%0], [%1], 16;" :: "r"(dst), "l"(src));
}
#define CP_COMMIT() asm volatile("cp.async.commit_group;" ::: "memory")
#define CP_WAIT1() asm volatile("cp.async.wait_group 1;" ::: "memory")
#define CP_WAIT0() asm volatile("cp.async.wait_group 0;" ::: "memory")

__device__ __forceinline__ uint32_t smem_u32(const void* p) {
  uint32_t a;
  asm("{ .reg .u64 t; cvta.to.shared.u64 t, %1; cvt.u32.u64 %0, t; }" : "=r"(a) : "l"(p));
  return a;
}

// ---------------------------------------------------------------------------
// Kernel 0: fused prep (blocks 0..63: W2 -> fp16 [n][k]) +
//           qproj (blocks 64..191: q@W1 + b1 + b2, split-k pairs)
// ---------------------------------------------------------------------------
__global__ void __launch_bounds__(256) prep_kernel(
    const float* __restrict__ W2, const float* __restrict__ query,
    const float* __restrict__ W1, const float* __restrict__ b1,
    const float* __restrict__ b2) {
  __shared__ float tile[64][72];
  __shared__ float qs[DD];
  int tid = threadIdx.x;
  if (blockIdx.x < 64) {
    int kb = (blockIdx.x & 7) * 64, nb = (blockIdx.x >> 3) * 64;
#pragma unroll
    for (int i = 0; i < 4; i++) {
      int t2 = tid + i * 256;
      int r = t2 >> 4, q = t2 & 15;
      float4 v = *(const float4*)(W2 + (size_t)(kb + r) * DD + nb + q * 4);
      *(float4*)&tile[r][q * 4] = v;
    }
    __syncthreads();
#pragma unroll
    for (int i = 0; i < 2; i++) {
      int t2 = tid + i * 256;
      int n = t2 >> 3, q = t2 & 7;
      uint32_t h[4];
#pragma unroll
      for (int e = 0; e < 4; e++) {
        __half2 hh = __floats2half2_rn(tile[q * 8 + e * 2 + 0][n],
                                       tile[q * 8 + e * 2 + 1][n]);
        h[e] = *reinterpret_cast<uint32_t*>(&hh);
      }
      size_t off = (size_t)(nb + n) * DD + kb + q * 8;
      *(uint4*)(g_w2f + off) = make_uint4(h[0], h[1], h[2], h[3]);
    }
  } else {
    int j = blockIdx.x - 64;
    int b = j >> 2, qn = j & 3;
    for (int i = tid; i < DD; i += 256) qs[i] = query[b * DD + i];
    __syncthreads();
    int n = qn * 128 + (tid >> 1);
    int k0 = (tid & 1) * 256;
    float acc = 0.f;
#pragma unroll 8
    for (int k = 0; k < 256; k++) acc = fmaf(qs[k0 + k], W1[(k0 + k) * DD + n], acc);
    acc += __shfl_xor_sync(0xffffffffu, acc, 1);
    if (!(tid & 1)) g_qadd[b * DD + n] = acc + b1[n] + b2[n];
  }
}

// ---------------------------------------------------------------------------
// Kernel 2: score GEMM — single fp16 term. Block: 128 rows resident,
// warp tile 32x64 (4 m-warps x 2 n-warps), W2 streamed cp.async 2-stage
// with 128-k stages.
// ---------------------------------------------------------------------------
#define A_STRIDE 1040          // (512+8) fp16 * 2 bytes
#define AH_OFF 0               // 128*1040 = 133120
#define BST_OFF 133120
#define B_RSTRIDE 272          // (128+8) fp16 * 2 bytes
#define B_STAGE 34816          // 128 rows * 272
#define Q_OFF 202752           // 133120 + 2*34816
#define V_OFF 204800
#define P_OFF 206848           // 256 floats
#define SMEM_TOTAL 207872

__global__ void __launch_bounds__(256, 1) score_mma_kernel(
    const float* __restrict__ values, const float* __restrict__ Vv,
    const float* __restrict__ bv) {
  extern __shared__ char smem[];
  const uint32_t sb = smem_u32(smem);
  const int tid = threadIdx.x;
  const int wid = tid >> 5, lane = tid & 31;
  const int gid = lane >> 2, tig = lane & 3;
  const int wm = wid & 3, wn = wid >> 2;  // 4 m-warps x 2 n-warps
  const int m0 = blockIdx.x * 128;
  const int b = m0 >> 12;

  float* qsh = (float*)(smem + Q_OFF);
  float* vsh = (float*)(smem + V_OFF);
  float* part = (float*)(smem + P_OFF);

  // ---- issue B stage0 for nc=0 first (overlaps A conversion) ----
  {
    uint32_t st = sb + BST_OFF;
#pragma unroll
    for (int i = 0; i < 8; i++) {
      int t2 = tid + i * 256;
      int r = t2 >> 4, q = t2 & 15;
      cp16(st + r * B_RSTRIDE + q * 16, g_w2f + (size_t)r * DD + q * 8);
    }
    CP_COMMIT();
  }

  // ---- A fill: 128 rows x 512 k -> fp16 plane ----
  for (int task = tid; task < 8192; task += 256) {
    int r = task >> 6, g = task & 63;
    const float4* p4 = (const float4*)(values + (size_t)(m0 + r) * DD + g * 8);
    float4 x0 = p4[0], x1 = p4[1];
    __half2 h0 = __floats2half2_rn(x0.x, x0.y);
    __half2 h1 = __floats2half2_rn(x0.z, x0.w);
    __half2 h2 = __floats2half2_rn(x1.x, x1.y);
    __half2 h3 = __floats2half2_rn(x1.z, x1.w);
    *(uint4*)(smem + AH_OFF + r * A_STRIDE + g * 16) =
        make_uint4(*(uint32_t*)&h0, *(uint32_t*)&h1, *(uint32_t*)&h2, *(uint32_t*)&h3);
  }
  for (int i = tid; i < DD; i += 256) {
    qsh[i] = g_qadd[b * DD + i];
    vsh[i] = Vv[i];
  }

  // ldmatrix per-lane addresses
  const int a_row = ((lane >> 3) & 1) * 8 + (lane & 7);
  const int a_col = (lane >> 4) * 16;
  const uint32_t aH_addr = sb + AH_OFF + (wm * 32 + a_row) * A_STRIDE + a_col;
  const int b_row = ((lane >> 4) & 1) * 8 + (lane & 7);
  const int b_col = ((lane >> 3) & 1) * 16;
  const uint32_t b_off = (wn * 64 + b_row) * B_RSTRIDE + b_col;

  float rowsum[4] = {0.f, 0.f, 0.f, 0.f};

  for (int nc = 0; nc < 4; ++nc) {
    float acc[2][8][4];
#pragma unroll
    for (int mi = 0; mi < 2; mi++)
#pragma unroll
      for (int ni = 0; ni < 8; ni++)
#pragma unroll
        for (int j = 0; j < 4; j++) acc[mi][ni][j] = 0.f;

    const unsigned short* Bg = g_w2f + (size_t)(nc * 128) * DD;

    for (int kt = 0; kt < 4; ++kt) {
      if (kt < 3) {
        uint32_t st = sb + BST_OFF + ((kt + 1) & 1) * B_STAGE;
        const unsigned short* Bk = Bg + (kt + 1) * 128;
#pragma unroll
        for (int i = 0; i < 8; i++) {
          int t2 = tid + i * 256;
          int r = t2 >> 4, q = t2 & 15;
          cp16(st + r * B_RSTRIDE + q * 16, Bk + (size_t)r * DD + q * 8);
        }
        CP_COMMIT();
        CP_WAIT1();
      } else {
        CP_WAIT0();
      }
      __syncthreads();  // stage kt ready (and A ready on first pass)

      const uint32_t stage = sb + BST_OFF + (kt & 1) * B_STAGE;
#pragma unroll
      for (int k16 = 0; k16 < 8; ++k16) {
        int kg = kt * 128 + k16 * 16;
        uint32_t aH[2][4], bH[4][4];
        ldsm_x4(aH[0], aH_addr + kg * 2);
        ldsm_x4(aH[1], aH_addr + 16 * A_STRIDE + kg * 2);
        uint32_t bbase = stage + b_off + k16 * 32;
        ldsm_x4(bH[0], bbase);
        ldsm_x4(bH[1], bbase + 16 * B_RSTRIDE);
        ldsm_x4(bH[2], bbase + 32 * B_RSTRIDE);
        ldsm_x4(bH[3], bbase + 48 * B_RSTRIDE);
#pragma unroll
        for (int mi = 0; mi < 2; mi++)
#pragma unroll
          for (int ni = 0; ni < 8; ni++)
            mma_f16(acc[mi][ni], aH[mi], &bH[ni >> 1][(ni & 1) * 2]);
      }
      __syncthreads();  // all readers done before stage is overwritten
    }

    // prefetch next nc's stage0 (both buffers free now)
    if (nc < 3) {
      uint32_t st = sb + BST_OFF;
      const unsigned short* Bn = g_w2f + (size_t)((nc + 1) * 128) * DD;
#pragma unroll
      for (int i = 0; i < 8; i++) {
        int t2 = tid + i * 256;
        int r = t2 >> 4, q = t2 & 15;
        cp16(st + r * B_RSTRIDE + q * 16, Bn + (size_t)r * DD + q * 8);
      }
      CP_COMMIT();
    }

    // epilogue for this 128-col chunk (tanh.approx: 1 MUFU per element)
#pragma unroll
    for (int mi = 0; mi < 2; mi++)
#pragma unroll
      for (int ni = 0; ni < 8; ni++)
#pragma unroll
        for (int j = 0; j < 4; j++) {
          int n = nc * 128 + wn * 64 + ni * 8 + tig * 2 + (j & 1);
          float h = tanh_fast(acc[mi][ni][j] + qsh[n]);
          rowsum[mi * 2 + (j >> 1)] = fmaf(h, vsh[n], rowsum[mi * 2 + (j >> 1)]);
        }
  }

#pragma unroll
  for (int i = 0; i < 4; i++) {
    rowsum[i] += __shfl_xor_sync(0xffffffffu, rowsum[i], 1);
    rowsum[i] += __shfl_xor_sync(0xffffffffu, rowsum[i], 2);
  }
  if (tig == 0) {
#pragma unroll
    for (int mi = 0; mi < 2; mi++)
#pragma unroll
      for (int ri = 0; ri < 2; ri++) {
        int row = wm * 32 + mi * 16 + ri * 8 + gid;
        part[wn * 128 + row] = rowsum[mi * 2 + ri];
      }
  }
  __syncthreads();
  if (tid < 128) {
    g_scores[m0 + tid] = part[tid] + part[128 + tid] + bv[0];
  }
}

// ---------------------------------------------------------------------------
// Kernel 3: per-batch max and 1/sum of exp
// ---------------------------------------------------------------------------
__global__ void __launch_bounds__(256) maxsum_kernel() {
  int b = blockIdx.x;
  const float* sc = g_scores + b * SS;
  __shared__ float redm[8];
  __shared__ float reds[8];
  __shared__ float bm;
  int tid = threadIdx.x, lane = tid & 31, w = tid >> 5;

  float m = -1e30f;
  for (int i = tid; i < SS; i += 256) m = fmaxf(m, sc[i]);
#pragma unroll
  for (int o = 16; o; o >>= 1) m = fmaxf(m, __shfl_xor_sync(0xffffffffu, m, o));
  if (lane == 0) redm[w] = m;
  __syncthreads();
  if (tid == 0) {
    float v = redm[0];
#pragma unroll
    for (int i = 1; i < 8; i++) v = fmaxf(v, redm[i]);
    bm = v;
  }
  __syncthreads();
  m = bm;

  float sum = 0.f;
  for (int i = tid; i < SS; i += 256) sum += expf(sc[i] - m);
#pragma unroll
  for (int o = 16; o; o >>= 1) sum += __shfl_xor_sync(0xffffffffu, sum, o);
  if (lane == 0) reds[w] = sum;
  __syncthreads();
  if (tid == 0) {
    float v = 0.f;
#pragma unroll
    for (int i = 0; i < 8; i++) v += reds[i];
    g_ms[2 * b] = m;
    g_ms[2 * b + 1] = 1.0f / v;
  }
}

// ---------------------------------------------------------------------------
// Kernel 4: context partials, attn written in-flight. Block = (s-chunk of 128,
// batch); 128 threads x float4 covers the full 512-d row (coalesced 2KB/row).
// ---------------------------------------------------------------------------
#define SCH 32
__global__ void __launch_bounds__(128) ctx_partial_kernel(
    const float* __restrict__ values, float* __restrict__ out) {
  const int t = threadIdx.x;
  const int chunk = blockIdx.x;   // 0..31
  const int b = blockIdx.y;
  const float m = g_ms[2 * b], inv = g_ms[2 * b + 1];
  const int s0 = chunk * (SS / SCH);
  const float* sc = g_scores + (size_t)b * SS + s0;
  float* attn = out + BB * DD + (size_t)b * SS + s0;
  const float4* vb = (const float4*)(values + ((size_t)b * SS + s0) * DD) + t;

  // one attn element per thread (128 rows per chunk, 128 threads)
  attn[t] = __expf(sc[t] - m) * inv;

  float4 acc = make_float4(0.f, 0.f, 0.f, 0.f);
#pragma unroll 4
  for (int s = 0; s < SS / SCH; s++) {
    float p = __expf(sc[s] - m) * inv;
    float4 v = vb[(size_t)s * (DD / 4)];
    acc.x = fmaf(p, v.x, acc.x);
    acc.y = fmaf(p, v.y, acc.y);
    acc.z = fmaf(p, v.z, acc.z);
    acc.w = fmaf(p, v.w, acc.w);
  }
  *((float4*)(g_partial + ((size_t)(b * SCH + chunk)) * DD) + t) = acc;
}

__global__ void __launch_bounds__(256) ctx_reduce_kernel(float* __restrict__ out) {
  int idx = blockIdx.x * 256 + threadIdx.x;  // over B*D/4 float4s
  if (idx >= BB * DD / 4) return;
  int b = idx / (DD / 4);
  int d4 = idx % (DD / 4);
  float4 acc = make_float4(0.f, 0.f, 0.f, 0.f);
#pragma unroll
  for (int p = 0; p < SCH; p++) {
    float4 v = *((const float4*)(g_partial + ((size_t)(b * SCH + p)) * DD) + d4);
    acc.x += v.x;
    acc.y += v.y;
    acc.z += v.z;
    acc.w += v.w;
  }
  *((float4*)out + idx) = acc;
}

// ---------------------------------------------------------------------------
extern "C" void kernel_launch(void* const* d_in, const int* in_sizes, int n_in,
                              void* d_out, int out_size) {
  const float* query = (const float*)d_in[0];
  const float* values = (const float*)d_in[1];
  const float* W1 = (const float*)d_in[2];
  const float* b1 = (const float*)d_in[3];
  const float* W2 = (const float*)d_in[4];
  const float* b2 = (const float*)d_in[5];
  const float* Vv = (const float*)d_in[6];
  const float* bv = (const float*)d_in[7];
  float* out = (float*)d_out;

  cudaFuncSetAttribute(score_mma_kernel,
                       cudaFuncAttributeMaxDynamicSharedMemorySize, SMEM_TOTAL);

  prep_kernel<<<192, 256>>>(W2, query, W1, b1, b2);
  score_mma_kernel<<<(BB * SS) / 128, 256, SMEM_TOTAL>>>(values, Vv, bv);
  maxsum_kernel<<<BB, 256>>>();
  ctx_partial_kernel<<<dim3(SCH, BB), 128>>>(values, out);
  ctx_reduce_kernel<<<(BB * DD / 4 + 255) / 256, 256>>>(out);
}

// round 10
// speedup vs baseline: 4.9357x; 1.0328x over previous
#include <cuda_runtime.h>
#include <cuda_fp16.h>
#include <math.h>
#include <cstdint>

#define BB 32
#define SS 4096
#define DD 512

// ---------------------------------------------------------------------------
// scratch (no allocation allowed)
// ---------------------------------------------------------------------------
__device__ float g_qadd[BB * DD];           // q@W1 + b1 + b2
__device__ float g_scores[BB * SS];         // logits
__device__ float g_partial[BB * 64 * DD];   // context partials
__device__ float g_msp[BB * 8 * 2];         // per-(batch,chunk) max / expsum
__device__ float g_ms[2 * BB];              // per-batch max, 1/sum
__device__ unsigned short g_w2f[DD * DD];   // fp16 W2, [n][k] k-contiguous

// ---------------------------------------------------------------------------
__device__ __forceinline__ float tanh_fast(float x) {
  float r;
  asm("tanh.approx.f32 %0, %1;" : "=f"(r) : "f"(x));
  return r;
}

__device__ __forceinline__ void mma_f16(float* c, const uint32_t* a, const uint32_t* b) {
  asm volatile(
      "mma.sync.aligned.m16n8k16.row.col.f32.f16.f16.f32 "
      "{%0,%1,%2,%3},{%4,%5,%6,%7},{%8,%9},{%0,%1,%2,%3};"
      : "+f"(c[0]), "+f"(c[1]), "+f"(c[2]), "+f"(c[3])
      : "r"(a[0]), "r"(a[1]), "r"(a[2]), "r"(a[3]), "r"(b[0]), "r"(b[1]));
}

__device__ __forceinline__ void ldsm_x4(uint32_t* r, uint32_t addr) {
  asm volatile("ldmatrix.sync.aligned.m8n8.x4.shared.b16 {%0,%1,%2,%3}, [%4];"
               : "=r"(r[0]), "=r"(r[1]), "=r"(r[2]), "=r"(r[3])
               : "r"(addr));
}

__device__ __forceinline__ void cp16(uint32_t dst, const void* src) {
  asm volatile("cp.async.cg.shared.global [%0], [%1], 16;" :: "r"(dst), "l"(src));
}
#define CP_COMMIT() asm volatile("cp.async.commit_group;" ::: "memory")
#define CP_WAIT1() asm volatile("cp.async.wait_group 1;" ::: "memory")
#define CP_WAIT0() asm volatile("cp.async.wait_group 0;" ::: "memory")

__device__ __forceinline__ uint32_t smem_u32(const void* p) {
  uint32_t a;
  asm("{ .reg .u64 t; cvta.to.shared.u64 t, %1; cvt.u32.u64 %0, t; }" : "=r"(a) : "l"(p));
  return a;
}

// ---------------------------------------------------------------------------
// Kernel 0: fused prep (blocks 0..63: W2 -> fp16 [n][k]) +
//           qproj (blocks 64..191: q@W1 + b1 + b2, split-k pairs)
// ---------------------------------------------------------------------------
__global__ void __launch_bounds__(256) prep_kernel(
    const float* __restrict__ W2, const float* __restrict__ query,
    const float* __restrict__ W1, const float* __restrict__ b1,
    const float* __restrict__ b2) {
  __shared__ float tile[64][72];
  __shared__ float qs[DD];
  int tid = threadIdx.x;
  if (blockIdx.x < 64) {
    int kb = (blockIdx.x & 7) * 64, nb = (blockIdx.x >> 3) * 64;
#pragma unroll
    for (int i = 0; i < 4; i++) {
      int t2 = tid + i * 256;
      int r = t2 >> 4, q = t2 & 15;
      float4 v = *(const float4*)(W2 + (size_t)(kb + r) * DD + nb + q * 4);
      *(float4*)&tile[r][q * 4] = v;
    }
    __syncthreads();
#pragma unroll
    for (int i = 0; i < 2; i++) {
      int t2 = tid + i * 256;
      int n = t2 >> 3, q = t2 & 7;
      uint32_t h[4];
#pragma unroll
      for (int e = 0; e < 4; e++) {
        __half2 hh = __floats2half2_rn(tile[q * 8 + e * 2 + 0][n],
                                       tile[q * 8 + e * 2 + 1][n]);
        h[e] = *reinterpret_cast<uint32_t*>(&hh);
      }
      size_t off = (size_t)(nb + n) * DD + kb + q * 8;
      *(uint4*)(g_w2f + off) = make_uint4(h[0], h[1], h[2], h[3]);
    }
  } else {
    int j = blockIdx.x - 64;
    int b = j >> 2, qn = j & 3;
    for (int i = tid; i < DD; i += 256) qs[i] = query[b * DD + i];
    __syncthreads();
    int n = qn * 128 + (tid >> 1);
    int k0 = (tid & 1) * 256;
    float acc = 0.f;
#pragma unroll 8
    for (int k = 0; k < 256; k++) acc = fmaf(qs[k0 + k], W1[(k0 + k) * DD + n], acc);
    acc += __shfl_xor_sync(0xffffffffu, acc, 1);
    if (!(tid & 1)) g_qadd[b * DD + n] = acc + b1[n] + b2[n];
  }
}

// ---------------------------------------------------------------------------
// Kernel 2: score GEMM — single fp16 term. Block: 128 rows resident,
// warp tile 32x64 (4 m-warps x 2 n-warps), W2 streamed cp.async 2-stage
// with 128-k stages.
// ---------------------------------------------------------------------------
#define A_STRIDE 1040          // (512+8) fp16 * 2 bytes
#define AH_OFF 0               // 128*1040 = 133120
#define BST_OFF 133120
#define B_RSTRIDE 272          // (128+8) fp16 * 2 bytes
#define B_STAGE 34816          // 128 rows * 272
#define Q_OFF 202752           // 133120 + 2*34816
#define V_OFF 204800
#define P_OFF 206848           // 256 floats
#define SMEM_TOTAL 207872

__global__ void __launch_bounds__(256, 1) score_mma_kernel(
    const float* __restrict__ values, const float* __restrict__ Vv,
    const float* __restrict__ bv) {
  extern __shared__ char smem[];
  const uint32_t sb = smem_u32(smem);
  const int tid = threadIdx.x;
  const int wid = tid >> 5, lane = tid & 31;
  const int gid = lane >> 2, tig = lane & 3;
  const int wm = wid & 3, wn = wid >> 2;  // 4 m-warps x 2 n-warps
  const int m0 = blockIdx.x * 128;
  const int b = m0 >> 12;

  float* qsh = (float*)(smem + Q_OFF);
  float* vsh = (float*)(smem + V_OFF);
  float* part = (float*)(smem + P_OFF);

  // ---- issue B stage0 for nc=0 first (overlaps A conversion) ----
  {
    uint32_t st = sb + BST_OFF;
#pragma unroll
    for (int i = 0; i < 8; i++) {
      int t2 = tid + i * 256;
      int r = t2 >> 4, q = t2 & 15;
      cp16(st + r * B_RSTRIDE + q * 16, g_w2f + (size_t)r * DD + q * 8);
    }
    CP_COMMIT();
  }

  // ---- A fill: 128 rows x 512 k -> fp16 plane ----
  for (int task = tid; task < 8192; task += 256) {
    int r = task >> 6, g = task & 63;
    const float4* p4 = (const float4*)(values + (size_t)(m0 + r) * DD + g * 8);
    float4 x0 = p4[0], x1 = p4[1];
    __half2 h0 = __floats2half2_rn(x0.x, x0.y);
    __half2 h1 = __floats2half2_rn(x0.z, x0.w);
    __half2 h2 = __floats2half2_rn(x1.x, x1.y);
    __half2 h3 = __floats2half2_rn(x1.z, x1.w);
    *(uint4*)(smem + AH_OFF + r * A_STRIDE + g * 16) =
        make_uint4(*(uint32_t*)&h0, *(uint32_t*)&h1, *(uint32_t*)&h2, *(uint32_t*)&h3);
  }
  for (int i = tid; i < DD; i += 256) {
    qsh[i] = g_qadd[b * DD + i];
    vsh[i] = Vv[i];
  }

  // ldmatrix per-lane addresses
  const int a_row = ((lane >> 3) & 1) * 8 + (lane & 7);
  const int a_col = (lane >> 4) * 16;
  const uint32_t aH_addr = sb + AH_OFF + (wm * 32 + a_row) * A_STRIDE + a_col;
  const int b_row = ((lane >> 4) & 1) * 8 + (lane & 7);
  const int b_col = ((lane >> 3) & 1) * 16;
  const uint32_t b_off = (wn * 64 + b_row) * B_RSTRIDE + b_col;

  float rowsum[4] = {0.f, 0.f, 0.f, 0.f};

  for (int nc = 0; nc < 4; ++nc) {
    float acc[2][8][4];
#pragma unroll
    for (int mi = 0; mi < 2; mi++)
#pragma unroll
      for (int ni = 0; ni < 8; ni++)
#pragma unroll
        for (int j = 0; j < 4; j++) acc[mi][ni][j] = 0.f;

    const unsigned short* Bg = g_w2f + (size_t)(nc * 128) * DD;

    for (int kt = 0; kt < 4; ++kt) {
      if (kt < 3) {
        uint32_t st = sb + BST_OFF + ((kt + 1) & 1) * B_STAGE;
        const unsigned short* Bk = Bg + (kt + 1) * 128;
#pragma unroll
        for (int i = 0; i < 8; i++) {
          int t2 = tid + i * 256;
          int r = t2 >> 4, q = t2 & 15;
          cp16(st + r * B_RSTRIDE + q * 16, Bk + (size_t)r * DD + q * 8);
        }
        CP_COMMIT();
        CP_WAIT1();
      } else {
        CP_WAIT0();
      }
      __syncthreads();  // stage kt ready (and A ready on first pass)

      const uint32_t stage = sb + BST_OFF + (kt & 1) * B_STAGE;
#pragma unroll
      for (int k16 = 0; k16 < 8; ++k16) {
        int kg = kt * 128 + k16 * 16;
        uint32_t aH[2][4], bH[4][4];
        ldsm_x4(aH[0], aH_addr + kg * 2);
        ldsm_x4(aH[1], aH_addr + 16 * A_STRIDE + kg * 2);
        uint32_t bbase = stage + b_off + k16 * 32;
        ldsm_x4(bH[0], bbase);
        ldsm_x4(bH[1], bbase + 16 * B_RSTRIDE);
        ldsm_x4(bH[2], bbase + 32 * B_RSTRIDE);
        ldsm_x4(bH[3], bbase + 48 * B_RSTRIDE);
#pragma unroll
        for (int mi = 0; mi < 2; mi++)
#pragma unroll
          for (int ni = 0; ni < 8; ni++)
            mma_f16(acc[mi][ni], aH[mi], &bH[ni >> 1][(ni & 1) * 2]);
      }
      __syncthreads();  // all readers done before stage is overwritten
    }

    // prefetch next nc's stage0 (both buffers free now)
    if (nc < 3) {
      uint32_t st = sb + BST_OFF;
      const unsigned short* Bn = g_w2f + (size_t)((nc + 1) * 128) * DD;
#pragma unroll
      for (int i = 0; i < 8; i++) {
        int t2 = tid + i * 256;
        int r = t2 >> 4, q = t2 & 15;
        cp16(st + r * B_RSTRIDE + q * 16, Bn + (size_t)r * DD + q * 8);
      }
      CP_COMMIT();
    }

    // epilogue for this 128-col chunk (tanh.approx: 1 MUFU per element)
#pragma unroll
    for (int mi = 0; mi < 2; mi++)
#pragma unroll
      for (int ni = 0; ni < 8; ni++)
#pragma unroll
        for (int j = 0; j < 4; j++) {
          int n = nc * 128 + wn * 64 + ni * 8 + tig * 2 + (j & 1);
          float h = tanh_fast(acc[mi][ni][j] + qsh[n]);
          rowsum[mi * 2 + (j >> 1)] = fmaf(h, vsh[n], rowsum[mi * 2 + (j >> 1)]);
        }
  }

#pragma unroll
  for (int i = 0; i < 4; i++) {
    rowsum[i] += __shfl_xor_sync(0xffffffffu, rowsum[i], 1);
    rowsum[i] += __shfl_xor_sync(0xffffffffu, rowsum[i], 2);
  }
  if (tig == 0) {
#pragma unroll
    for (int mi = 0; mi < 2; mi++)
#pragma unroll
      for (int ri = 0; ri < 2; ri++) {
        int row = wm * 32 + mi * 16 + ri * 8 + gid;
        part[wn * 128 + row] = rowsum[mi * 2 + ri];
      }
  }
  __syncthreads();
  if (tid < 128) {
    g_scores[m0 + tid] = part[tid] + part[128 + tid] + bv[0];
  }
}

// ---------------------------------------------------------------------------
// Kernel 3a: per-(batch, 512-chunk) local max and expsum  (grid 32x8)
// ---------------------------------------------------------------------------
__global__ void __launch_bounds__(256) maxsum_part_kernel() {
  int b = blockIdx.x, c = blockIdx.y;
  const float* sc = g_scores + (size_t)b * SS + c * 512;
  __shared__ float red[8];
  __shared__ float bm;
  int tid = threadIdx.x, lane = tid & 31, w = tid >> 5;

  float m = fmaxf(sc[tid], sc[tid + 256]);
#pragma unroll
  for (int o = 16; o; o >>= 1) m = fmaxf(m, __shfl_xor_sync(0xffffffffu, m, o));
  if (lane == 0) red[w] = m;
  __syncthreads();
  if (tid == 0) {
    float v = red[0];
#pragma unroll
    for (int i = 1; i < 8; i++) v = fmaxf(v, red[i]);
    bm = v;
  }
  __syncthreads();
  m = bm;

  float sum = expf(sc[tid] - m) + expf(sc[tid + 256] - m);
#pragma unroll
  for (int o = 16; o; o >>= 1) sum += __shfl_xor_sync(0xffffffffu, sum, o);
  if (lane == 0) red[w] = sum;
  __syncthreads();
  if (tid == 0) {
    float v = 0.f;
#pragma unroll
    for (int i = 0; i < 8; i++) v += red[i];
    g_msp[(b * 8 + c) * 2] = m;
    g_msp[(b * 8 + c) * 2 + 1] = v;
  }
}

// Kernel 3b: combine 8 partials per batch -> (max, 1/sum)   (grid 32, 32thr)
__global__ void __launch_bounds__(32) maxsum_comb_kernel() {
  int b = blockIdx.x;
  int lane = threadIdx.x;
  float m = (lane < 8) ? g_msp[(b * 8 + lane) * 2] : -1e30f;
  float s = (lane < 8) ? g_msp[(b * 8 + lane) * 2 + 1] : 0.f;
  float M = m;
#pragma unroll
  for (int o = 4; o; o >>= 1) M = fmaxf(M, __shfl_xor_sync(0xffffffffu, M, o));
  float sv = s * expf(m - M);
#pragma unroll
  for (int o = 4; o; o >>= 1) sv += __shfl_xor_sync(0xffffffffu, sv, o);
  if (lane == 0) {
    g_ms[2 * b] = M;
    g_ms[2 * b + 1] = 1.0f / sv;
  }
}

// ---------------------------------------------------------------------------
// Kernel 4: context partials, attn written in-flight. Block = (s-chunk of 64,
// batch); 128 threads x float4 covers the full 512-d row (coalesced 2KB/row).
// ---------------------------------------------------------------------------
#define SCH 64
__global__ void __launch_bounds__(128) ctx_partial_kernel(
    const float* __restrict__ values, float* __restrict__ out) {
  const int t = threadIdx.x;
  const int chunk = blockIdx.x;   // 0..63
  const int b = blockIdx.y;
  const float m = g_ms[2 * b], inv = g_ms[2 * b + 1];
  const int s0 = chunk * (SS / SCH);
  const float* sc = g_scores + (size_t)b * SS + s0;
  float* attn = out + BB * DD + (size_t)b * SS + s0;
  const float4* vb = (const float4*)(values + ((size_t)b * SS + s0) * DD) + t;

  // attn elements for this chunk (64 rows, 128 threads)
  if (t < SS / SCH) attn[t] = __expf(sc[t] - m) * inv;

  float4 acc = make_float4(0.f, 0.f, 0.f, 0.f);
#pragma unroll 8
  for (int s = 0; s < SS / SCH; s++) {
    float p = __expf(sc[s] - m) * inv;
    float4 v = vb[(size_t)s * (DD / 4)];
    acc.x = fmaf(p, v.x, acc.x);
    acc.y = fmaf(p, v.y, acc.y);
    acc.z = fmaf(p, v.z, acc.z);
    acc.w = fmaf(p, v.w, acc.w);
  }
  *((float4*)(g_partial + ((size_t)(b * SCH + chunk)) * DD) + t) = acc;
}

__global__ void __launch_bounds__(256) ctx_reduce_kernel(float* __restrict__ out) {
  int idx = blockIdx.x * 256 + threadIdx.x;  // over B*D/4 float4s
  if (idx >= BB * DD / 4) return;
  int b = idx / (DD / 4);
  int d4 = idx % (DD / 4);
  float4 acc = make_float4(0.f, 0.f, 0.f, 0.f);
#pragma unroll
  for (int p = 0; p < SCH; p++) {
    float4 v = *((const float4*)(g_partial + ((size_t)(b * SCH + p)) * DD) + d4);
    acc.x += v.x;
    acc.y += v.y;
    acc.z += v.z;
    acc.w += v.w;
  }
  *((float4*)out + idx) = acc;
}

// ---------------------------------------------------------------------------
extern "C" void kernel_launch(void* const* d_in, const int* in_sizes, int n_in,
                              void* d_out, int out_size) {
  const float* query = (const float*)d_in[0];
  const float* values = (const float*)d_in[1];
  const float* W1 = (const float*)d_in[2];
  const float* b1 = (const float*)d_in[3];
  const float* W2 = (const float*)d_in[4];
  const float* b2 = (const float*)d_in[5];
  const float* Vv = (const float*)d_in[6];
  const float* bv = (const float*)d_in[7];
  float* out = (float*)d_out;

  cudaFuncSetAttribute(score_mma_kernel,
                       cudaFuncAttributeMaxDynamicSharedMemorySize, SMEM_TOTAL);

  prep_kernel<<<192, 256>>>(W2, query, W1, b1, b2);
  score_mma_kernel<<<(BB * SS) / 128, 256, SMEM_TOTAL>>>(values, Vv, bv);
  maxsum_part_kernel<<<dim3(BB, 8), 256>>>();
  maxsum_comb_kernel<<<BB, 32>>>();
  ctx_partial_kernel<<<dim3(SCH, BB), 128>>>(values, out);
  ctx_reduce_kernel<<<(BB * DD / 4 + 255) / 256, 256>>>(out);
}

// round 11
// speedup vs baseline: 4.9935x; 1.0117x over previous
#include <cuda_runtime.h>
#include <cuda_fp16.h>
#include <math.h>
#include <cstdint>

#define BB 32
#define SS 4096
#define DD 512

// ---------------------------------------------------------------------------
// scratch (no allocation allowed)
// ---------------------------------------------------------------------------
__device__ float g_qadd[BB * DD];           // q@W1 + b1 + b2
__device__ float g_scores[BB * SS];         // logits
__device__ float g_partial[BB * 64 * DD];   // context partials
__device__ float g_msp[BB * 32 * 2];        // per-score-block (max, expsum)
__device__ unsigned short g_w2f[DD * DD];   // fp16 W2, [n][k] k-contiguous

// ---------------------------------------------------------------------------
__device__ __forceinline__ float tanh_fast(float x) {
  float r;
  asm("tanh.approx.f32 %0, %1;" : "=f"(r) : "f"(x));
  return r;
}

__device__ __forceinline__ void mma_f16(float* c, const uint32_t* a, const uint32_t* b) {
  asm volatile(
      "mma.sync.aligned.m16n8k16.row.col.f32.f16.f16.f32 "
      "{%0,%1,%2,%3},{%4,%5,%6,%7},{%8,%9},{%0,%1,%2,%3};"
      : "+f"(c[0]), "+f"(c[1]), "+f"(c[2]), "+f"(c[3])
      : "r"(a[0]), "r"(a[1]), "r"(a[2]), "r"(a[3]), "r"(b[0]), "r"(b[1]));
}

__device__ __forceinline__ void ldsm_x4(uint32_t* r, uint32_t addr) {
  asm volatile("ldmatrix.sync.aligned.m8n8.x4.shared.b16 {%0,%1,%2,%3}, [%4];"
               : "=r"(r[0]), "=r"(r[1]), "=r"(r[2]), "=r"(r[3])
               : "r"(addr));
}

__device__ __forceinline__ void cp16(uint32_t dst, const void* src) {
  asm volatile("cp.async.cg.shared.global [%0], [%1], 16;" :: "r"(dst), "l"(src));
}
#define CP_COMMIT() asm volatile("cp.async.commit_group;" ::: "memory")
#define CP_WAIT1() asm volatile("cp.async.wait_group 1;" ::: "memory")
#define CP_WAIT0() asm volatile("cp.async.wait_group 0;" ::: "memory")

__device__ __forceinline__ uint32_t smem_u32(const void* p) {
  uint32_t a;
  asm("{ .reg .u64 t; cvta.to.shared.u64 t, %1; cvt.u32.u64 %0, t; }" : "=r"(a) : "l"(p));
  return a;
}

// ---------------------------------------------------------------------------
// Kernel 0: fused prep (blocks 0..63: W2 -> fp16 [n][k]) +
//           qproj (blocks 64..191: q@W1 + b1 + b2, split-k pairs)
// ---------------------------------------------------------------------------
__global__ void __launch_bounds__(256) prep_kernel(
    const float* __restrict__ W2, const float* __restrict__ query,
    const float* __restrict__ W1, const float* __restrict__ b1,
    const float* __restrict__ b2) {
  __shared__ float tile[64][72];
  __shared__ float qs[DD];
  int tid = threadIdx.x;
  if (blockIdx.x < 64) {
    int kb = (blockIdx.x & 7) * 64, nb = (blockIdx.x >> 3) * 64;
#pragma unroll
    for (int i = 0; i < 4; i++) {
      int t2 = tid + i * 256;
      int r = t2 >> 4, q = t2 & 15;
      float4 v = *(const float4*)(W2 + (size_t)(kb + r) * DD + nb + q * 4);
      *(float4*)&tile[r][q * 4] = v;
    }
    __syncthreads();
#pragma unroll
    for (int i = 0; i < 2; i++) {
      int t2 = tid + i * 256;
      int n = t2 >> 3, q = t2 & 7;
      uint32_t h[4];
#pragma unroll
      for (int e = 0; e < 4; e++) {
        __half2 hh = __floats2half2_rn(tile[q * 8 + e * 2 + 0][n],
                                       tile[q * 8 + e * 2 + 1][n]);
        h[e] = *reinterpret_cast<uint32_t*>(&hh);
      }
      size_t off = (size_t)(nb + n) * DD + kb + q * 8;
      *(uint4*)(g_w2f + off) = make_uint4(h[0], h[1], h[2], h[3]);
    }
  } else {
    int j = blockIdx.x - 64;
    int b = j >> 2, qn = j & 3;
    for (int i = tid; i < DD; i += 256) qs[i] = query[b * DD + i];
    __syncthreads();
    int n = qn * 128 + (tid >> 1);
    int k0 = (tid & 1) * 256;
    float acc = 0.f;
#pragma unroll 8
    for (int k = 0; k < 256; k++) acc = fmaf(qs[k0 + k], W1[(k0 + k) * DD + n], acc);
    acc += __shfl_xor_sync(0xffffffffu, acc, 1);
    if (!(tid & 1)) g_qadd[b * DD + n] = acc + b1[n] + b2[n];
  }
}

// ---------------------------------------------------------------------------
// Kernel 2: score GEMM — single fp16 term. Block: 128 rows resident,
// warp tile 32x64, W2 streamed cp.async 2-stage with 128-k stages.
// Epilogue also emits per-block (max, expsum) to g_msp.
// ---------------------------------------------------------------------------
#define A_STRIDE 1040          // (512+8) fp16 * 2 bytes
#define AH_OFF 0               // 128*1040 = 133120
#define BST_OFF 133120
#define B_RSTRIDE 272          // (128+8) fp16 * 2 bytes
#define B_STAGE 34816          // 128 rows * 272
#define Q_OFF 202752           // 133120 + 2*34816
#define V_OFF 204800
#define P_OFF 206848           // 256 floats + 16 scratch
#define SMEM_TOTAL 207936

__global__ void __launch_bounds__(256, 1) score_mma_kernel(
    const float* __restrict__ values, const float* __restrict__ Vv,
    const float* __restrict__ bv) {
  extern __shared__ char smem[];
  const uint32_t sb = smem_u32(smem);
  const int tid = threadIdx.x;
  const int wid = tid >> 5, lane = tid & 31;
  const int gid = lane >> 2, tig = lane & 3;
  const int wm = wid & 3, wn = wid >> 2;  // 4 m-warps x 2 n-warps
  const int m0 = blockIdx.x * 128;
  const int b = m0 >> 12;

  float* qsh = (float*)(smem + Q_OFF);
  float* vsh = (float*)(smem + V_OFF);
  float* part = (float*)(smem + P_OFF);
  float* red = part + 256;  // 16 floats scratch

  // ---- issue B stage0 for nc=0 first (overlaps A conversion) ----
  {
    uint32_t st = sb + BST_OFF;
#pragma unroll
    for (int i = 0; i < 8; i++) {
      int t2 = tid + i * 256;
      int r = t2 >> 4, q = t2 & 15;
      cp16(st + r * B_RSTRIDE + q * 16, g_w2f + (size_t)r * DD + q * 8);
    }
    CP_COMMIT();
  }

  // ---- A fill: 128 rows x 512 k -> fp16 plane ----
  for (int task = tid; task < 8192; task += 256) {
    int r = task >> 6, g = task & 63;
    const float4* p4 = (const float4*)(values + (size_t)(m0 + r) * DD + g * 8);
    float4 x0 = p4[0], x1 = p4[1];
    __half2 h0 = __floats2half2_rn(x0.x, x0.y);
    __half2 h1 = __floats2half2_rn(x0.z, x0.w);
    __half2 h2 = __floats2half2_rn(x1.x, x1.y);
    __half2 h3 = __floats2half2_rn(x1.z, x1.w);
    *(uint4*)(smem + AH_OFF + r * A_STRIDE + g * 16) =
        make_uint4(*(uint32_t*)&h0, *(uint32_t*)&h1, *(uint32_t*)&h2, *(uint32_t*)&h3);
  }
  for (int i = tid; i < DD; i += 256) {
    qsh[i] = g_qadd[b * DD + i];
    vsh[i] = Vv[i];
  }

  // ldmatrix per-lane addresses
  const int a_row = ((lane >> 3) & 1) * 8 + (lane & 7);
  const int a_col = (lane >> 4) * 16;
  const uint32_t aH_addr = sb + AH_OFF + (wm * 32 + a_row) * A_STRIDE + a_col;
  const int b_row = ((lane >> 4) & 1) * 8 + (lane & 7);
  const int b_col = ((lane >> 3) & 1) * 16;
  const uint32_t b_off = (wn * 64 + b_row) * B_RSTRIDE + b_col;

  float rowsum[4] = {0.f, 0.f, 0.f, 0.f};

  for (int nc = 0; nc < 4; ++nc) {
    float acc[2][8][4];
#pragma unroll
    for (int mi = 0; mi < 2; mi++)
#pragma unroll
      for (int ni = 0; ni < 8; ni++)
#pragma unroll
        for (int j = 0; j < 4; j++) acc[mi][ni][j] = 0.f;

    const unsigned short* Bg = g_w2f + (size_t)(nc * 128) * DD;

    for (int kt = 0; kt < 4; ++kt) {
      if (kt < 3) {
        uint32_t st = sb + BST_OFF + ((kt + 1) & 1) * B_STAGE;
        const unsigned short* Bk = Bg + (kt + 1) * 128;
#pragma unroll
        for (int i = 0; i < 8; i++) {
          int t2 = tid + i * 256;
          int r = t2 >> 4, q = t2 & 15;
          cp16(st + r * B_RSTRIDE + q * 16, Bk + (size_t)r * DD + q * 8);
        }
        CP_COMMIT();
        CP_WAIT1();
      } else {
        CP_WAIT0();
      }
      __syncthreads();  // stage kt ready (and A ready on first pass)

      const uint32_t stage = sb + BST_OFF + (kt & 1) * B_STAGE;
#pragma unroll
      for (int k16 = 0; k16 < 8; ++k16) {
        int kg = kt * 128 + k16 * 16;
        uint32_t aH[2][4], bH[4][4];
        ldsm_x4(aH[0], aH_addr + kg * 2);
        ldsm_x4(aH[1], aH_addr + 16 * A_STRIDE + kg * 2);
        uint32_t bbase = stage + b_off + k16 * 32;
        ldsm_x4(bH[0], bbase);
        ldsm_x4(bH[1], bbase + 16 * B_RSTRIDE);
        ldsm_x4(bH[2], bbase + 32 * B_RSTRIDE);
        ldsm_x4(bH[3], bbase + 48 * B_RSTRIDE);
#pragma unroll
        for (int mi = 0; mi < 2; mi++)
#pragma unroll
          for (int ni = 0; ni < 8; ni++)
            mma_f16(acc[mi][ni], aH[mi], &bH[ni >> 1][(ni & 1) * 2]);
      }
      __syncthreads();  // all readers done before stage is overwritten
    }

    // prefetch next nc's stage0 (both buffers free now)
    if (nc < 3) {
      uint32_t st = sb + BST_OFF;
      const unsigned short* Bn = g_w2f + (size_t)((nc + 1) * 128) * DD;
#pragma unroll
      for (int i = 0; i < 8; i++) {
        int t2 = tid + i * 256;
        int r = t2 >> 4, q = t2 & 15;
        cp16(st + r * B_RSTRIDE + q * 16, Bn + (size_t)r * DD + q * 8);
      }
      CP_COMMIT();
    }

    // epilogue for this 128-col chunk (tanh.approx: 1 MUFU per element)
#pragma unroll
    for (int mi = 0; mi < 2; mi++)
#pragma unroll
      for (int ni = 0; ni < 8; ni++)
#pragma unroll
        for (int j = 0; j < 4; j++) {
          int n = nc * 128 + wn * 64 + ni * 8 + tig * 2 + (j & 1);
          float h = tanh_fast(acc[mi][ni][j] + qsh[n]);
          rowsum[mi * 2 + (j >> 1)] = fmaf(h, vsh[n], rowsum[mi * 2 + (j >> 1)]);
        }
  }

#pragma unroll
  for (int i = 0; i < 4; i++) {
    rowsum[i] += __shfl_xor_sync(0xffffffffu, rowsum[i], 1);
    rowsum[i] += __shfl_xor_sync(0xffffffffu, rowsum[i], 2);
  }
  if (tig == 0) {
#pragma unroll
    for (int mi = 0; mi < 2; mi++)
#pragma unroll
      for (int ri = 0; ri < 2; ri++) {
        int row = wm * 32 + mi * 16 + ri * 8 + gid;
        part[wn * 128 + row] = rowsum[mi * 2 + ri];
      }
  }
  __syncthreads();
  float sval = -1e30f;
  if (tid < 128) {
    sval = part[tid] + part[128 + tid] + bv[0];
    g_scores[m0 + tid] = sval;
  }

  // ---- per-block (max, expsum) for softmax ----
  float mv = sval;
#pragma unroll
  for (int o = 16; o; o >>= 1) mv = fmaxf(mv, __shfl_xor_sync(0xffffffffu, mv, o));
  __syncthreads();  // part reads complete before red reuse
  if (lane == 0) red[wid] = mv;
  __syncthreads();
  float mloc = red[0];
#pragma unroll
  for (int i = 1; i < 8; i++) mloc = fmaxf(mloc, red[i]);
  float ev = (tid < 128) ? __expf(sval - mloc) : 0.f;
#pragma unroll
  for (int o = 16; o; o >>= 1) ev += __shfl_xor_sync(0xffffffffu, ev, o);
  __syncthreads();
  if (lane == 0) red[8 + wid] = ev;
  __syncthreads();
  if (tid == 0) {
    float v = 0.f;
#pragma unroll
    for (int i = 0; i < 8; i++) v += red[8 + i];
    g_msp[blockIdx.x * 2] = mloc;
    g_msp[blockIdx.x * 2 + 1] = v;
  }
}

// ---------------------------------------------------------------------------
// Kernel 4: context partials, attn written in-flight; inline softmax combine.
// Block = (s-chunk of 64, batch); 128 threads x float4 (coalesced 2KB/row).
// ---------------------------------------------------------------------------
#define SCH 64
__global__ void __launch_bounds__(128) ctx_partial_kernel(
    const float* __restrict__ values, float* __restrict__ out) {
  const int t = threadIdx.x;
  const int chunk = blockIdx.x;   // 0..63
  const int b = blockIdx.y;
  __shared__ float sM, sInv;
  __shared__ float ps[SS / SCH];

  // combine this batch's 32 (max, expsum) pairs
  if (t < 32) {
    float m = g_msp[(b * 32 + t) * 2];
    float sv = g_msp[(b * 32 + t) * 2 + 1];
    float M = m;
#pragma unroll
    for (int o = 16; o; o >>= 1) M = fmaxf(M, __shfl_xor_sync(0xffffffffu, M, o));
    float z = sv * __expf(m - M);
#pragma unroll
    for (int o = 16; o; o >>= 1) z += __shfl_xor_sync(0xffffffffu, z, o);
    if (t == 0) {
      sM = M;
      sInv = 1.0f / z;
    }
  }
  __syncthreads();
  const float m = sM, inv = sInv;

  const int s0 = chunk * (SS / SCH);
  const float* sc = g_scores + (size_t)b * SS + s0;
  float* attn = out + BB * DD + (size_t)b * SS + s0;
  const float4* vb = (const float4*)(values + ((size_t)b * SS + s0) * DD) + t;

  // probabilities for this chunk (64 values), shared by all threads
  if (t < SS / SCH) {
    float p = __expf(sc[t] - m) * inv;
    ps[t] = p;
    attn[t] = p;
  }
  __syncthreads();

  float4 acc = make_float4(0.f, 0.f, 0.f, 0.f);
#pragma unroll 8
  for (int s = 0; s < SS / SCH; s++) {
    float p = ps[s];
    float4 v = vb[(size_t)s * (DD / 4)];
    acc.x = fmaf(p, v.x, acc.x);
    acc.y = fmaf(p, v.y, acc.y);
    acc.z = fmaf(p, v.z, acc.z);
    acc.w = fmaf(p, v.w, acc.w);
  }
  *((float4*)(g_partial + ((size_t)(b * SCH + chunk)) * DD) + t) = acc;
}

__global__ void __launch_bounds__(256) ctx_reduce_kernel(float* __restrict__ out) {
  int idx = blockIdx.x * 256 + threadIdx.x;  // over B*D/4 float4s
  if (idx >= BB * DD / 4) return;
  int b = idx / (DD / 4);
  int d4 = idx % (DD / 4);
  float4 acc = make_float4(0.f, 0.f, 0.f, 0.f);
#pragma unroll
  for (int p = 0; p < SCH; p++) {
    float4 v = *((const float4*)(g_partial + ((size_t)(b * SCH + p)) * DD) + d4);
    acc.x += v.x;
    acc.y += v.y;
    acc.z += v.z;
    acc.w += v.w;
  }
  *((float4*)out + idx) = acc;
}

// ---------------------------------------------------------------------------
extern "C" void kernel_launch(void* const* d_in, const int* in_sizes, int n_in,
                              void* d_out, int out_size) {
  const float* query = (const float*)d_in[0];
  const float* values = (const float*)d_in[1];
  const float* W1 = (const float*)d_in[2];
  const float* b1 = (const float*)d_in[3];
  const float* W2 = (const float*)d_in[4];
  const float* b2 = (const float*)d_in[5];
  const float* Vv = (const float*)d_in[6];
  const float* bv = (const float*)d_in[7];
  float* out = (float*)d_out;

  cudaFuncSetAttribute(score_mma_kernel,
                       cudaFuncAttributeMaxDynamicSharedMemorySize, SMEM_TOTAL);

  prep_kernel<<<192, 256>>>(W2, query, W1, b1, b2);
  score_mma_kernel<<<(BB * SS) / 128, 256, SMEM_TOTAL>>>(values, Vv, bv);
  ctx_partial_kernel<<<dim3(SCH, BB), 128>>>(values, out);
  ctx_reduce_kernel<<<(BB * DD / 4 + 255) / 256, 256>>>(out);
}

// round 12
// speedup vs baseline: 5.0000x; 1.0013x over previous
#include <cuda_runtime.h>
#include <cuda_fp16.h>
#include <math.h>
#include <cstdint>

#define BB 32
#define SS 4096
#define DD 512

// ---------------------------------------------------------------------------
// scratch (no allocation allowed)
// ---------------------------------------------------------------------------
__device__ float g_qadd[BB * DD];           // q@W1 + b1 + b2
__device__ float g_scores[BB * SS];         // logits
__device__ float g_partial[BB * 64 * DD];   // context partials
__device__ float g_msp[BB * 32 * 2];        // per-score-block (max, expsum)
__device__ int g_cnt[BB];                   // arrival counters (reset by reducer)
__device__ unsigned short g_w2f[DD * DD];   // fp16 W2, [n][k] k-contiguous

// ---------------------------------------------------------------------------
__device__ __forceinline__ float tanh_fast(float x) {
  float r;
  asm("tanh.approx.f32 %0, %1;" : "=f"(r) : "f"(x));
  return r;
}

__device__ __forceinline__ void mma_f16(float* c, const uint32_t* a, const uint32_t* b) {
  asm volatile(
      "mma.sync.aligned.m16n8k16.row.col.f32.f16.f16.f32 "
      "{%0,%1,%2,%3},{%4,%5,%6,%7},{%8,%9},{%0,%1,%2,%3};"
      : "+f"(c[0]), "+f"(c[1]), "+f"(c[2]), "+f"(c[3])
      : "r"(a[0]), "r"(a[1]), "r"(a[2]), "r"(a[3]), "r"(b[0]), "r"(b[1]));
}

__device__ __forceinline__ void ldsm_x4(uint32_t* r, uint32_t addr) {
  asm volatile("ldmatrix.sync.aligned.m8n8.x4.shared.b16 {%0,%1,%2,%3}, [%4];"
               : "=r"(r[0]), "=r"(r[1]), "=r"(r[2]), "=r"(r[3])
               : "r"(addr));
}

__device__ __forceinline__ void cp16(uint32_t dst, const void* src) {
  asm volatile("cp.async.cg.shared.global [%0], [%1], 16;" :: "r"(dst), "l"(src));
}
#define CP_COMMIT() asm volatile("cp.async.commit_group;" ::: "memory")
#define CP_WAIT1() asm volatile("cp.async.wait_group 1;" ::: "memory")
#define CP_WAIT0() asm volatile("cp.async.wait_group 0;" ::: "memory")

__device__ __forceinline__ uint32_t smem_u32(const void* p) {
  uint32_t a;
  asm("{ .reg .u64 t; cvta.to.shared.u64 t, %1; cvt.u32.u64 %0, t; }" : "=r"(a) : "l"(p));
  return a;
}

// ---------------------------------------------------------------------------
// Kernel 0: fused prep (blocks 0..63: W2 -> fp16 [n][k]) +
//           qproj (blocks 64..191: q@W1 + b1 + b2, split-k pairs)
// ---------------------------------------------------------------------------
__global__ void __launch_bounds__(256) prep_kernel(
    const float* __restrict__ W2, const float* __restrict__ query,
    const float* __restrict__ W1, const float* __restrict__ b1,
    const float* __restrict__ b2) {
  __shared__ float tile[64][72];
  __shared__ float qs[DD];
  int tid = threadIdx.x;
  if (blockIdx.x < 64) {
    int kb = (blockIdx.x & 7) * 64, nb = (blockIdx.x >> 3) * 64;
#pragma unroll
    for (int i = 0; i < 4; i++) {
      int t2 = tid + i * 256;
      int r = t2 >> 4, q = t2 & 15;
      float4 v = *(const float4*)(W2 + (size_t)(kb + r) * DD + nb + q * 4);
      *(float4*)&tile[r][q * 4] = v;
    }
    __syncthreads();
#pragma unroll
    for (int i = 0; i < 2; i++) {
      int t2 = tid + i * 256;
      int n = t2 >> 3, q = t2 & 7;
      uint32_t h[4];
#pragma unroll
      for (int e = 0; e < 4; e++) {
        __half2 hh = __floats2half2_rn(tile[q * 8 + e * 2 + 0][n],
                                       tile[q * 8 + e * 2 + 1][n]);
        h[e] = *reinterpret_cast<uint32_t*>(&hh);
      }
      size_t off = (size_t)(nb + n) * DD + kb + q * 8;
      *(uint4*)(g_w2f + off) = make_uint4(h[0], h[1], h[2], h[3]);
    }
  } else {
    int j = blockIdx.x - 64;
    int b = j >> 2, qn = j & 3;
    for (int i = tid; i < DD; i += 256) qs[i] = query[b * DD + i];
    __syncthreads();
    int n = qn * 128 + (tid >> 1);
    int k0 = (tid & 1) * 256;
    float acc = 0.f;
#pragma unroll 8
    for (int k = 0; k < 256; k++) acc = fmaf(qs[k0 + k], W1[(k0 + k) * DD + n], acc);
    acc += __shfl_xor_sync(0xffffffffu, acc, 1);
    if (!(tid & 1)) g_qadd[b * DD + n] = acc + b1[n] + b2[n];
  }
}

// ---------------------------------------------------------------------------
// Kernel 2: score GEMM — single fp16 term. Block: 128 rows resident,
// warp tile 32x64, W2 streamed cp.async 2-stage with 128-k stages.
// Epilogue also emits per-block (max, expsum) to g_msp.
// ---------------------------------------------------------------------------
#define A_STRIDE 1040          // (512+8) fp16 * 2 bytes
#define AH_OFF 0               // 128*1040 = 133120
#define BST_OFF 133120
#define B_RSTRIDE 272          // (128+8) fp16 * 2 bytes
#define B_STAGE 34816          // 128 rows * 272
#define Q_OFF 202752           // 133120 + 2*34816
#define V_OFF 204800
#define P_OFF 206848           // 256 floats + 16 scratch
#define SMEM_TOTAL 207936

__global__ void __launch_bounds__(256, 1) score_mma_kernel(
    const float* __restrict__ values, const float* __restrict__ Vv,
    const float* __restrict__ bv) {
  extern __shared__ char smem[];
  const uint32_t sb = smem_u32(smem);
  const int tid = threadIdx.x;
  const int wid = tid >> 5, lane = tid & 31;
  const int gid = lane >> 2, tig = lane & 3;
  const int wm = wid & 3, wn = wid >> 2;  // 4 m-warps x 2 n-warps
  const int m0 = blockIdx.x * 128;
  const int b = m0 >> 12;

  float* qsh = (float*)(smem + Q_OFF);
  float* vsh = (float*)(smem + V_OFF);
  float* part = (float*)(smem + P_OFF);
  float* red = part + 256;  // 16 floats scratch

  // ---- issue B stage0 for nc=0 first (overlaps A conversion) ----
  {
    uint32_t st = sb + BST_OFF;
#pragma unroll
    for (int i = 0; i < 8; i++) {
      int t2 = tid + i * 256;
      int r = t2 >> 4, q = t2 & 15;
      cp16(st + r * B_RSTRIDE + q * 16, g_w2f + (size_t)r * DD + q * 8);
    }
    CP_COMMIT();
  }

  // ---- A fill: 128 rows x 512 k -> fp16 plane ----
  for (int task = tid; task < 8192; task += 256) {
    int r = task >> 6, g = task & 63;
    const float4* p4 = (const float4*)(values + (size_t)(m0 + r) * DD + g * 8);
    float4 x0 = p4[0], x1 = p4[1];
    __half2 h0 = __floats2half2_rn(x0.x, x0.y);
    __half2 h1 = __floats2half2_rn(x0.z, x0.w);
    __half2 h2 = __floats2half2_rn(x1.x, x1.y);
    __half2 h3 = __floats2half2_rn(x1.z, x1.w);
    *(uint4*)(smem + AH_OFF + r * A_STRIDE + g * 16) =
        make_uint4(*(uint32_t*)&h0, *(uint32_t*)&h1, *(uint32_t*)&h2, *(uint32_t*)&h3);
  }
  for (int i = tid; i < DD; i += 256) {
    qsh[i] = g_qadd[b * DD + i];
    vsh[i] = Vv[i];
  }

  // ldmatrix per-lane addresses
  const int a_row = ((lane >> 3) & 1) * 8 + (lane & 7);
  const int a_col = (lane >> 4) * 16;
  const uint32_t aH_addr = sb + AH_OFF + (wm * 32 + a_row) * A_STRIDE + a_col;
  const int b_row = ((lane >> 4) & 1) * 8 + (lane & 7);
  const int b_col = ((lane >> 3) & 1) * 16;
  const uint32_t b_off = (wn * 64 + b_row) * B_RSTRIDE + b_col;

  float rowsum[4] = {0.f, 0.f, 0.f, 0.f};

  for (int nc = 0; nc < 4; ++nc) {
    float acc[2][8][4];
#pragma unroll
    for (int mi = 0; mi < 2; mi++)
#pragma unroll
      for (int ni = 0; ni < 8; ni++)
#pragma unroll
        for (int j = 0; j < 4; j++) acc[mi][ni][j] = 0.f;

    const unsigned short* Bg = g_w2f + (size_t)(nc * 128) * DD;

    for (int kt = 0; kt < 4; ++kt) {
      if (kt < 3) {
        uint32_t st = sb + BST_OFF + ((kt + 1) & 1) * B_STAGE;
        const unsigned short* Bk = Bg + (kt + 1) * 128;
#pragma unroll
        for (int i = 0; i < 8; i++) {
          int t2 = tid + i * 256;
          int r = t2 >> 4, q = t2 & 15;
          cp16(st + r * B_RSTRIDE + q * 16, Bk + (size_t)r * DD + q * 8);
        }
        CP_COMMIT();
        CP_WAIT1();
      } else {
        CP_WAIT0();
      }
      __syncthreads();  // stage kt ready (and A ready on first pass)

      const uint32_t stage = sb + BST_OFF + (kt & 1) * B_STAGE;
#pragma unroll
      for (int k16 = 0; k16 < 8; ++k16) {
        int kg = kt * 128 + k16 * 16;
        uint32_t aH[2][4], bH[4][4];
        ldsm_x4(aH[0], aH_addr + kg * 2);
        ldsm_x4(aH[1], aH_addr + 16 * A_STRIDE + kg * 2);
        uint32_t bbase = stage + b_off + k16 * 32;
        ldsm_x4(bH[0], bbase);
        ldsm_x4(bH[1], bbase + 16 * B_RSTRIDE);
        ldsm_x4(bH[2], bbase + 32 * B_RSTRIDE);
        ldsm_x4(bH[3], bbase + 48 * B_RSTRIDE);
#pragma unroll
        for (int mi = 0; mi < 2; mi++)
#pragma unroll
          for (int ni = 0; ni < 8; ni++)
            mma_f16(acc[mi][ni], aH[mi], &bH[ni >> 1][(ni & 1) * 2]);
      }
      __syncthreads();  // all readers done before stage is overwritten
    }

    // prefetch next nc's stage0 (both buffers free now)
    if (nc < 3) {
      uint32_t st = sb + BST_OFF;
      const unsigned short* Bn = g_w2f + (size_t)((nc + 1) * 128) * DD;
#pragma unroll
      for (int i = 0; i < 8; i++) {
        int t2 = tid + i * 256;
        int r = t2 >> 4, q = t2 & 15;
        cp16(st + r * B_RSTRIDE + q * 16, Bn + (size_t)r * DD + q * 8);
      }
      CP_COMMIT();
    }

    // epilogue for this 128-col chunk (tanh.approx: 1 MUFU per element)
#pragma unroll
    for (int mi = 0; mi < 2; mi++)
#pragma unroll
      for (int ni = 0; ni < 8; ni++)
#pragma unroll
        for (int j = 0; j < 4; j++) {
          int n = nc * 128 + wn * 64 + ni * 8 + tig * 2 + (j & 1);
          float h = tanh_fast(acc[mi][ni][j] + qsh[n]);
          rowsum[mi * 2 + (j >> 1)] = fmaf(h, vsh[n], rowsum[mi * 2 + (j >> 1)]);
        }
  }

#pragma unroll
  for (int i = 0; i < 4; i++) {
    rowsum[i] += __shfl_xor_sync(0xffffffffu, rowsum[i], 1);
    rowsum[i] += __shfl_xor_sync(0xffffffffu, rowsum[i], 2);
  }
  if (tig == 0) {
#pragma unroll
    for (int mi = 0; mi < 2; mi++)
#pragma unroll
      for (int ri = 0; ri < 2; ri++) {
        int row = wm * 32 + mi * 16 + ri * 8 + gid;
        part[wn * 128 + row] = rowsum[mi * 2 + ri];
      }
  }
  __syncthreads();
  float sval = -1e30f;
  if (tid < 128) {
    sval = part[tid] + part[128 + tid] + bv[0];
    g_scores[m0 + tid] = sval;
  }

  // ---- per-block (max, expsum) for softmax ----
  float mv = sval;
#pragma unroll
  for (int o = 16; o; o >>= 1) mv = fmaxf(mv, __shfl_xor_sync(0xffffffffu, mv, o));
  __syncthreads();  // part reads complete before red reuse
  if (lane == 0) red[wid] = mv;
  __syncthreads();
  float mloc = red[0];
#pragma unroll
  for (int i = 1; i < 8; i++) mloc = fmaxf(mloc, red[i]);
  float ev = (tid < 128) ? __expf(sval - mloc) : 0.f;
#pragma unroll
  for (int o = 16; o; o >>= 1) ev += __shfl_xor_sync(0xffffffffu, ev, o);
  __syncthreads();
  if (lane == 0) red[8 + wid] = ev;
  __syncthreads();
  if (tid == 0) {
    float v = 0.f;
#pragma unroll
    for (int i = 0; i < 8; i++) v += red[8 + i];
    g_msp[blockIdx.x * 2] = mloc;
    g_msp[blockIdx.x * 2 + 1] = v;
  }
}

// ---------------------------------------------------------------------------
// Kernel 4: context partials + fused last-block reduction. Block = (s-chunk
// of 64, batch); 128 threads x float4 (coalesced 2KB/row). The last block
// of each batch (arrival counter) reduces partials into d_out in fixed order.
// ---------------------------------------------------------------------------
#define SCH 64
__global__ void __launch_bounds__(128) ctx_partial_kernel(
    const float* __restrict__ values, float* __restrict__ out) {
  const int t = threadIdx.x;
  const int chunk = blockIdx.x;   // 0..63
  const int b = blockIdx.y;
  __shared__ float sM, sInv;
  __shared__ float ps[SS / SCH];
  __shared__ int sLast;

  // combine this batch's 32 (max, expsum) pairs
  if (t < 32) {
    float m = g_msp[(b * 32 + t) * 2];
    float sv = g_msp[(b * 32 + t) * 2 + 1];
    float M = m;
#pragma unroll
    for (int o = 16; o; o >>= 1) M = fmaxf(M, __shfl_xor_sync(0xffffffffu, M, o));
    float z = sv * __expf(m - M);
#pragma unroll
    for (int o = 16; o; o >>= 1) z += __shfl_xor_sync(0xffffffffu, z, o);
    if (t == 0) {
      sM = M;
      sInv = 1.0f / z;
    }
  }
  __syncthreads();
  const float m = sM, inv = sInv;

  const int s0 = chunk * (SS / SCH);
  const float* sc = g_scores + (size_t)b * SS + s0;
  float* attn = out + BB * DD + (size_t)b * SS + s0;
  const float4* vb = (const float4*)(values + ((size_t)b * SS + s0) * DD) + t;

  // probabilities for this chunk (64 values), shared by all threads
  if (t < SS / SCH) {
    float p = __expf(sc[t] - m) * inv;
    ps[t] = p;
    attn[t] = p;
  }
  __syncthreads();

  float4 acc = make_float4(0.f, 0.f, 0.f, 0.f);
#pragma unroll 8
  for (int s = 0; s < SS / SCH; s++) {
    float p = ps[s];
    float4 v = vb[(size_t)s * (DD / 4)];
    acc.x = fmaf(p, v.x, acc.x);
    acc.y = fmaf(p, v.y, acc.y);
    acc.z = fmaf(p, v.z, acc.z);
    acc.w = fmaf(p, v.w, acc.w);
  }
  *((float4*)(g_partial + ((size_t)(b * SCH + chunk)) * DD) + t) = acc;

  // ---- last block of this batch reduces all 64 partials (fixed order) ----
  __threadfence();
  if (t == 0) {
    int prev = atomicAdd(&g_cnt[b], 1);
    sLast = (prev == SCH - 1);
  }
  __syncthreads();
  if (sLast) {
    const float4* pp = (const float4*)(g_partial + (size_t)b * SCH * DD) + t;
    float4 r = make_float4(0.f, 0.f, 0.f, 0.f);
#pragma unroll 8
    for (int p = 0; p < SCH; p++) {
      float4 v = pp[(size_t)p * (DD / 4)];
      r.x += v.x;
      r.y += v.y;
      r.z += v.z;
      r.w += v.w;
    }
    *((float4*)out + b * (DD / 4) + t) = r;
    if (t == 0) g_cnt[b] = 0;  // reset for next graph replay
  }
}

// ---------------------------------------------------------------------------
extern "C" void kernel_launch(void* const* d_in, const int* in_sizes, int n_in,
                              void* d_out, int out_size) {
  const float* query = (const float*)d_in[0];
  const float* values = (const float*)d_in[1];
  const float* W1 = (const float*)d_in[2];
  const float* b1 = (const float*)d_in[3];
  const float* W2 = (const float*)d_in[4];
  const float* b2 = (const float*)d_in[5];
  const float* Vv = (const float*)d_in[6];
  const float* bv = (const float*)d_in[7];
  float* out = (float*)d_out;

  cudaFuncSetAttribute(score_mma_kernel,
                       cudaFuncAttributeMaxDynamicSharedMemorySize, SMEM_TOTAL);

  prep_kernel<<<192, 256>>>(W2, query, W1, b1, b2);
  score_mma_kernel<<<(BB * SS) / 128, 256, SMEM_TOTAL>>>(values, Vv, bv);
  ctx_partial_kernel<<<dim3(SCH, BB), 128>>>(values, out);
}

// round 14
// speedup vs baseline: 5.0970x; 1.0194x over previous
#include <cuda_runtime.h>
#include <cuda_fp16.h>
#include <math.h>
#include <cstdint>

#define BB 32
#define SS 4096
#define DD 512

// ---------------------------------------------------------------------------
// scratch (no allocation allowed)
// ---------------------------------------------------------------------------
__device__ float g_qadd[BB * DD];           // q@W1 + b1 + b2
__device__ float g_scores[BB * SS];         // logits
__device__ float g_partial[BB * 64 * DD];   // context partials
__device__ float g_msp[BB * 32 * 2];        // per-score-block (max, expsum)
__device__ unsigned short g_w2f[DD * DD];   // fp16 W2, [n][k] k-contiguous

// ---------------------------------------------------------------------------
__device__ __forceinline__ float tanh_fast(float x) {
  float r;
  asm("tanh.approx.f32 %0, %1;" : "=f"(r) : "f"(x));
  return r;
}

__device__ __forceinline__ void mma_f16(float* c, const uint32_t* a, const uint32_t* b) {
  asm volatile(
      "mma.sync.aligned.m16n8k16.row.col.f32.f16.f16.f32 "
      "{%0,%1,%2,%3},{%4,%5,%6,%7},{%8,%9},{%0,%1,%2,%3};"
      : "+f"(c[0]), "+f"(c[1]), "+f"(c[2]), "+f"(c[3])
      : "r"(a[0]), "r"(a[1]), "r"(a[2]), "r"(a[3]), "r"(b[0]), "r"(b[1]));
}

__device__ __forceinline__ void ldsm_x4(uint32_t* r, uint32_t addr) {
  asm volatile("ldmatrix.sync.aligned.m8n8.x4.shared.b16 {%0,%1,%2,%3}, [%4];"
               : "=r"(r[0]), "=r"(r[1]), "=r"(r[2]), "=r"(r[3])
               : "r"(addr));
}

__device__ __forceinline__ void cp16(uint32_t dst, const void* src) {
  asm volatile("cp.async.cg.shared.global [%0], [%1], 16;" :: "r"(dst), "l"(src));
}
#define CP_COMMIT() asm volatile("cp.async.commit_group;" ::: "memory")
#define CP_WAIT1() asm volatile("cp.async.wait_group 1;" ::: "memory")
#define CP_WAIT0() asm volatile("cp.async.wait_group 0;" ::: "memory")

__device__ __forceinline__ uint32_t smem_u32(const void* p) {
  uint32_t a;
  asm("{ .reg .u64 t; cvta.to.shared.u64 t, %1; cvt.u32.u64 %0, t; }" : "=r"(a) : "l"(p));
  return a;
}

// ---------------------------------------------------------------------------
// Kernel 0: fused prep.
//   blocks 0..127   : W2 -> fp16 [n][k] via smem transpose (64k x 32n tiles)
//   blocks 128..383 : qproj (b, 64-col n-chunk, 4-way split-k in-warp)
// ---------------------------------------------------------------------------
__global__ void __launch_bounds__(256) prep_kernel(
    const float* __restrict__ W2, const float* __restrict__ query,
    const float* __restrict__ W1, const float* __restrict__ b1,
    const float* __restrict__ b2) {
  __shared__ float tile[64][36];
  __shared__ float qs[DD];
  int tid = threadIdx.x;
  if (blockIdx.x < 128) {
    int kb = (blockIdx.x & 7) * 64, nb = (blockIdx.x >> 3) * 32;
#pragma unroll
    for (int i = 0; i < 2; i++) {
      int t2 = tid + i * 256;             // 512 = 64 krows * 8 float4
      int r = t2 >> 3, q = t2 & 7;
      float4 v = *(const float4*)(W2 + (size_t)(kb + r) * DD + nb + q * 4);
      *(float4*)&tile[r][q * 4] = v;
    }
    __syncthreads();
    {
      int n = tid >> 3, q = tid & 7;      // 256 = 32 nrows * 8 uint4
      uint32_t h[4];
#pragma unroll
      for (int e = 0; e < 4; e++) {
        __half2 hh = __floats2half2_rn(tile[q * 8 + e * 2 + 0][n],
                                       tile[q * 8 + e * 2 + 1][n]);
        h[e] = *reinterpret_cast<uint32_t*>(&hh);
      }
      size_t off = (size_t)(nb + n) * DD + kb + q * 8;
      *(uint4*)(g_w2f + off) = make_uint4(h[0], h[1], h[2], h[3]);
    }
  } else {
    int j = blockIdx.x - 128;             // 0..255
    int b = j >> 3, qn = j & 7;           // n chunk of 64
    for (int i = tid; i < DD; i += 256) qs[i] = query[b * DD + i];
    __syncthreads();
    int n = qn * 64 + (tid >> 2);
    int k0 = (tid & 3) * 128;
    float acc = 0.f;
#pragma unroll 8
    for (int k = 0; k < 128; k++) acc = fmaf(qs[k0 + k], W1[(k0 + k) * DD + n], acc);
    acc += __shfl_xor_sync(0xffffffffu, acc, 1);
    acc += __shfl_xor_sync(0xffffffffu, acc, 2);
    if (!(tid & 3)) g_qadd[b * DD + n] = acc + b1[n] + b2[n];
  }
}

// ---------------------------------------------------------------------------
// Kernel 2: score GEMM — single fp16 term. Block: 128 rows resident,
// warp tile 32x64, W2 streamed cp.async 2-stage with 128-k stages.
// Epilogue also emits per-block (max, expsum) to g_msp.
// ---------------------------------------------------------------------------
#define A_STRIDE 1040          // (512+8) fp16 * 2 bytes
#define AH_OFF 0               // 128*1040 = 133120
#define BST_OFF 133120
#define B_RSTRIDE 272          // (128+8) fp16 * 2 bytes
#define B_STAGE 34816          // 128 rows * 272
#define Q_OFF 202752           // 133120 + 2*34816
#define V_OFF 204800
#define P_OFF 206848           // 256 floats + 16 scratch
#define SMEM_TOTAL 207936

__global__ void __launch_bounds__(256, 1) score_mma_kernel(
    const float* __restrict__ values, const float* __restrict__ Vv,
    const float* __restrict__ bv) {
  extern __shared__ char smem[];
  const uint32_t sb = smem_u32(smem);
  const int tid = threadIdx.x;
  const int wid = tid >> 5, lane = tid & 31;
  const int gid = lane >> 2, tig = lane & 3;
  const int wm = wid & 3, wn = wid >> 2;  // 4 m-warps x 2 n-warps
  const int m0 = blockIdx.x * 128;
  const int b = m0 >> 12;

  float* qsh = (float*)(smem + Q_OFF);
  float* vsh = (float*)(smem + V_OFF);
  float* part = (float*)(smem + P_OFF);
  float* red = part + 256;  // 16 floats scratch

  // ---- issue B stage0 for nc=0 first (overlaps A conversion) ----
  {
    uint32_t st = sb + BST_OFF;
#pragma unroll
    for (int i = 0; i < 8; i++) {
      int t2 = tid + i * 256;
      int r = t2 >> 4, q = t2 & 15;
      cp16(st + r * B_RSTRIDE + q * 16, g_w2f + (size_t)r * DD + q * 8);
    }
    CP_COMMIT();
  }

  // ---- A fill: 128 rows x 512 k -> fp16 plane ----
  for (int task = tid; task < 8192; task += 256) {
    int r = task >> 6, g = task & 63;
    const float4* p4 = (const float4*)(values + (size_t)(m0 + r) * DD + g * 8);
    float4 x0 = p4[0], x1 = p4[1];
    __half2 h0 = __floats2half2_rn(x0.x, x0.y);
    __half2 h1 = __floats2half2_rn(x0.z, x0.w);
    __half2 h2 = __floats2half2_rn(x1.x, x1.y);
    __half2 h3 = __floats2half2_rn(x1.z, x1.w);
    *(uint4*)(smem + AH_OFF + r * A_STRIDE + g * 16) =
        make_uint4(*(uint32_t*)&h0, *(uint32_t*)&h1, *(uint32_t*)&h2, *(uint32_t*)&h3);
  }
  for (int i = tid; i < DD; i += 256) {
    qsh[i] = g_qadd[b * DD + i];
    vsh[i] = Vv[i];
  }

  // ldmatrix per-lane addresses
  const int a_row = ((lane >> 3) & 1) * 8 + (lane & 7);
  const int a_col = (lane >> 4) * 16;
  const uint32_t aH_addr = sb + AH_OFF + (wm * 32 + a_row) * A_STRIDE + a_col;
  const int b_row = ((lane >> 4) & 1) * 8 + (lane & 7);
  const int b_col = ((lane >> 3) & 1) * 16;
  const uint32_t b_off = (wn * 64 + b_row) * B_RSTRIDE + b_col;

  float rowsum[4] = {0.f, 0.f, 0.f, 0.f};

  for (int nc = 0; nc < 4; ++nc) {
    float acc[2][8][4];
#pragma unroll
    for (int mi = 0; mi < 2; mi++)
#pragma unroll
      for (int ni = 0; ni < 8; ni++)
#pragma unroll
        for (int j = 0; j < 4; j++) acc[mi][ni][j] = 0.f;

    const unsigned short* Bg = g_w2f + (size_t)(nc * 128) * DD;

    for (int kt = 0; kt < 4; ++kt) {
      if (kt < 3) {
        uint32_t st = sb + BST_OFF + ((kt + 1) & 1) * B_STAGE;
        const unsigned short* Bk = Bg + (kt + 1) * 128;
#pragma unroll
        for (int i = 0; i < 8; i++) {
          int t2 = tid + i * 256;
          int r = t2 >> 4, q = t2 & 15;
          cp16(st + r * B_RSTRIDE + q * 16, Bk + (size_t)r * DD + q * 8);
        }
        CP_COMMIT();
        CP_WAIT1();
      } else {
        CP_WAIT0();
      }
      __syncthreads();  // stage kt ready (and A ready on first pass)

      const uint32_t stage = sb + BST_OFF + (kt & 1) * B_STAGE;
#pragma unroll
      for (int k16 = 0; k16 < 8; ++k16) {
        int kg = kt * 128 + k16 * 16;
        uint32_t aH[2][4], bH[4][4];
        ldsm_x4(aH[0], aH_addr + kg * 2);
        ldsm_x4(aH[1], aH_addr + 16 * A_STRIDE + kg * 2);
        uint32_t bbase = stage + b_off + k16 * 32;
        ldsm_x4(bH[0], bbase);
        ldsm_x4(bH[1], bbase + 16 * B_RSTRIDE);
        ldsm_x4(bH[2], bbase + 32 * B_RSTRIDE);
        ldsm_x4(bH[3], bbase + 48 * B_RSTRIDE);
#pragma unroll
        for (int mi = 0; mi < 2; mi++)
#pragma unroll
          for (int ni = 0; ni < 8; ni++)
            mma_f16(acc[mi][ni], aH[mi], &bH[ni >> 1][(ni & 1) * 2]);
      }
      __syncthreads();  // all readers done before stage is overwritten
    }

    // prefetch next nc's stage0 (both buffers free now)
    if (nc < 3) {
      uint32_t st = sb + BST_OFF;
      const unsigned short* Bn = g_w2f + (size_t)((nc + 1) * 128) * DD;
#pragma unroll
      for (int i = 0; i < 8; i++) {
        int t2 = tid + i * 256;
        int r = t2 >> 4, q = t2 & 15;
        cp16(st + r * B_RSTRIDE + q * 16, Bn + (size_t)r * DD + q * 8);
      }
      CP_COMMIT();
    }

    // epilogue for this 128-col chunk (tanh.approx: 1 MUFU per element)
#pragma unroll
    for (int mi = 0; mi < 2; mi++)
#pragma unroll
      for (int ni = 0; ni < 8; ni++)
#pragma unroll
        for (int j = 0; j < 4; j++) {
          int n = nc * 128 + wn * 64 + ni * 8 + tig * 2 + (j & 1);
          float h = tanh_fast(acc[mi][ni][j] + qsh[n]);
          rowsum[mi * 2 + (j >> 1)] = fmaf(h, vsh[n], rowsum[mi * 2 + (j >> 1)]);
        }
  }

#pragma unroll
  for (int i = 0; i < 4; i++) {
    rowsum[i] += __shfl_xor_sync(0xffffffffu, rowsum[i], 1);
    rowsum[i] += __shfl_xor_sync(0xffffffffu, rowsum[i], 2);
  }
  if (tig == 0) {
#pragma unroll
    for (int mi = 0; mi < 2; mi++)
#pragma unroll
      for (int ri = 0; ri < 2; ri++) {
        int row = wm * 32 + mi * 16 + ri * 8 + gid;
        part[wn * 128 + row] = rowsum[mi * 2 + ri];
      }
  }
  __syncthreads();
  float sval = -1e30f;
  if (tid < 128) {
    sval = part[tid] + part[128 + tid] + bv[0];
    g_scores[m0 + tid] = sval;
  }

  // ---- per-block (max, expsum) for softmax ----
  float mv = sval;
#pragma unroll
  for (int o = 16; o; o >>= 1) mv = fmaxf(mv, __shfl_xor_sync(0xffffffffu, mv, o));
  __syncthreads();  // part reads complete before red reuse
  if (lane == 0) red[wid] = mv;
  __syncthreads();
  float mloc = red[0];
#pragma unroll
  for (int i = 1; i < 8; i++) mloc = fmaxf(mloc, red[i]);
  float ev = (tid < 128) ? __expf(sval - mloc) : 0.f;
#pragma unroll
  for (int o = 16; o; o >>= 1) ev += __shfl_xor_sync(0xffffffffu, ev, o);
  __syncthreads();
  if (lane == 0) red[8 + wid] = ev;
  __syncthreads();
  if (tid == 0) {
    float v = 0.f;
#pragma unroll
    for (int i = 0; i < 8; i++) v += red[8 + i];
    g_msp[blockIdx.x * 2] = mloc;
    g_msp[blockIdx.x * 2 + 1] = v;
  }
}

// ---------------------------------------------------------------------------
// Kernel 4: context partials, attn written in-flight; inline softmax combine.
// Block = (s-chunk of 64, batch); 128 threads x float4 (coalesced 2KB/row).
// ---------------------------------------------------------------------------
#define SCH 64
__global__ void __launch_bounds__(128) ctx_partial_kernel(
    const float* __restrict__ values, float* __restrict__ out) {
  const int t = threadIdx.x;
  const int chunk = blockIdx.x;   // 0..63
  const int b = blockIdx.y;
  __shared__ float sM, sInv;
  __shared__ float ps[SS / SCH];

  // combine this batch's 32 (max, expsum) pairs
  if (t < 32) {
    float m = g_msp[(b * 32 + t) * 2];
    float sv = g_msp[(b * 32 + t) * 2 + 1];
    float M = m;
#pragma unroll
    for (int o = 16; o; o >>= 1) M = fmaxf(M, __shfl_xor_sync(0xffffffffu, M, o));
    float z = sv * __expf(m - M);
#pragma unroll
    for (int o = 16; o; o >>= 1) z += __shfl_xor_sync(0xffffffffu, z, o);
    if (t == 0) {
      sM = M;
      sInv = 1.0f / z;
    }
  }
  __syncthreads();
  const float m = sM, inv = sInv;

  const int s0 = chunk * (SS / SCH);
  const float* sc = g_scores + (size_t)b * SS + s0;
  float* attn = out + BB * DD + (size_t)b * SS + s0;
  const float4* vb = (const float4*)(values + ((size_t)b * SS + s0) * DD) + t;

  // probabilities for this chunk (64 values), shared by all threads
  if (t < SS / SCH) {
    float p = __expf(sc[t] - m) * inv;
    ps[t] = p;
    attn[t] = p;
  }
  __syncthreads();

  float4 acc = make_float4(0.f, 0.f, 0.f, 0.f);
#pragma unroll 8
  for (int s = 0; s < SS / SCH; s++) {
    float p = ps[s];
    float4 v = vb[(size_t)s * (DD / 4)];
    acc.x = fmaf(p, v.x, acc.x);
    acc.y = fmaf(p, v.y, acc.y);
    acc.z = fmaf(p, v.z, acc.z);
    acc.w = fmaf(p, v.w, acc.w);
  }
  *((float4*)(g_partial + ((size_t)(b * SCH + chunk)) * DD) + t) = acc;
}

// Kernel 5: deterministic final reduce of partials -> context
__global__ void __launch_bounds__(256) ctx_reduce_kernel(float* __restrict__ out) {
  int idx = blockIdx.x * 256 + threadIdx.x;  // over B*D/4 float4s
  if (idx >= BB * DD / 4) return;
  int b = idx / (DD / 4);
  int d4 = idx % (DD / 4);
  float4 acc = make_float4(0.f, 0.f, 0.f, 0.f);
#pragma unroll
  for (int p = 0; p < SCH; p++) {
    float4 v = *((const float4*)(g_partial + ((size_t)(b * SCH + p)) * DD) + d4);
    acc.x += v.x;
    acc.y += v.y;
    acc.z += v.z;
    acc.w += v.w;
  }
  *((float4*)out + idx) = acc;
}

// ---------------------------------------------------------------------------
extern "C" void kernel_launch(void* const* d_in, const int* in_sizes, int n_in,
                              void* d_out, int out_size) {
  const float* query = (const float*)d_in[0];
  const float* values = (const float*)d_in[1];
  const float* W1 = (const float*)d_in[2];
  const float* b1 = (const float*)d_in[3];
  const float* W2 = (const float*)d_in[4];
  const float* b2 = (const float*)d_in[5];
  const float* Vv = (const float*)d_in[6];
  const float* bv = (const float*)d_in[7];
  float* out = (float*)d_out;

  cudaFuncSetAttribute(score_mma_kernel,
                       cudaFuncAttributeMaxDynamicSharedMemorySize, SMEM_TOTAL);

  prep_kernel<<<384, 256>>>(W2, query, W1, b1, b2);
  score_mma_kernel<<<(BB * SS) / 128, 256, SMEM_TOTAL>>>(values, Vv, bv);
  ctx_partial_kernel<<<dim3(SCH, BB), 128>>>(values, out);
  ctx_reduce_kernel<<<(BB * DD / 4 + 255) / 256, 256>>>(out);
}

// round 15
// speedup vs baseline: 5.1575x; 1.0119x over previous
#include <cuda_runtime.h>
#include <cuda_fp16.h>
#include <math.h>
#include <cstdint>

#define BB 32
#define SS 4096
#define DD 512

// ---------------------------------------------------------------------------
// scratch (no allocation allowed)
// ---------------------------------------------------------------------------
__device__ float g_qadd[BB * DD];           // q@W1 + b1 + b2
__device__ float g_scores[BB * SS];         // logits
__device__ float g_partial[BB * 64 * DD];   // context partials
__device__ float g_msp[BB * 32 * 2];        // per-score-block (max, expsum)
__device__ unsigned short g_w2f[DD * DD];   // fp16 W2, [n][k] k-contiguous

// ---------------------------------------------------------------------------
__device__ __forceinline__ float tanh_fast(float x) {
  float r;
  asm("tanh.approx.f32 %0, %1;" : "=f"(r) : "f"(x));
  return r;
}

__device__ __forceinline__ void mma_f16(float* c, const uint32_t* a, const uint32_t* b) {
  asm volatile(
      "mma.sync.aligned.m16n8k16.row.col.f32.f16.f16.f32 "
      "{%0,%1,%2,%3},{%4,%5,%6,%7},{%8,%9},{%0,%1,%2,%3};"
      : "+f"(c[0]), "+f"(c[1]), "+f"(c[2]), "+f"(c[3])
      : "r"(a[0]), "r"(a[1]), "r"(a[2]), "r"(a[3]), "r"(b[0]), "r"(b[1]));
}

__device__ __forceinline__ void ldsm_x4(uint32_t* r, uint32_t addr) {
  asm volatile("ldmatrix.sync.aligned.m8n8.x4.shared.b16 {%0,%1,%2,%3}, [%4];"
               : "=r"(r[0]), "=r"(r[1]), "=r"(r[2]), "=r"(r[3])
               : "r"(addr));
}

__device__ __forceinline__ void cp16(uint32_t dst, const void* src) {
  asm volatile("cp.async.cg.shared.global [%0], [%1], 16;" :: "r"(dst), "l"(src));
}
#define CP_COMMIT() asm volatile("cp.async.commit_group;" ::: "memory")
#define CP_WAIT1() asm volatile("cp.async.wait_group 1;" ::: "memory")
#define CP_WAIT0() asm volatile("cp.async.wait_group 0;" ::: "memory")

__device__ __forceinline__ uint32_t smem_u32(const void* p) {
  uint32_t a;
  asm("{ .reg .u64 t; cvta.to.shared.u64 t, %1; cvt.u32.u64 %0, t; }" : "=r"(a) : "l"(p));
  return a;
}

// ---------------------------------------------------------------------------
// Kernel 0: fused prep.
//   blocks 0..127   : W2 -> fp16 [n][k] via smem transpose (64k x 32n tiles)
//   blocks 128..383 : qproj (b, 64-col n-chunk, 4-way split-k in-warp)
// ---------------------------------------------------------------------------
__global__ void __launch_bounds__(256) prep_kernel(
    const float* __restrict__ W2, const float* __restrict__ query,
    const float* __restrict__ W1, const float* __restrict__ b1,
    const float* __restrict__ b2) {
  __shared__ float tile[64][36];
  __shared__ float qs[DD];
  int tid = threadIdx.x;
  if (blockIdx.x < 128) {
    int kb = (blockIdx.x & 7) * 64, nb = (blockIdx.x >> 3) * 32;
#pragma unroll
    for (int i = 0; i < 2; i++) {
      int t2 = tid + i * 256;             // 512 = 64 krows * 8 float4
      int r = t2 >> 3, q = t2 & 7;
      float4 v = *(const float4*)(W2 + (size_t)(kb + r) * DD + nb + q * 4);
      *(float4*)&tile[r][q * 4] = v;
    }
    __syncthreads();
    {
      int n = tid >> 3, q = tid & 7;      // 256 = 32 nrows * 8 uint4
      uint32_t h[4];
#pragma unroll
      for (int e = 0; e < 4; e++) {
        __half2 hh = __floats2half2_rn(tile[q * 8 + e * 2 + 0][n],
                                       tile[q * 8 + e * 2 + 1][n]);
        h[e] = *reinterpret_cast<uint32_t*>(&hh);
      }
      size_t off = (size_t)(nb + n) * DD + kb + q * 8;
      *(uint4*)(g_w2f + off) = make_uint4(h[0], h[1], h[2], h[3]);
    }
  } else {
    int j = blockIdx.x - 128;             // 0..255
    int b = j >> 3, qn = j & 7;           // n chunk of 64
    for (int i = tid; i < DD; i += 256) qs[i] = query[b * DD + i];
    __syncthreads();
    int n = qn * 64 + (tid >> 2);
    int k0 = (tid & 3) * 128;
    float acc = 0.f;
#pragma unroll 8
    for (int k = 0; k < 128; k++) acc = fmaf(qs[k0 + k], W1[(k0 + k) * DD + n], acc);
    acc += __shfl_xor_sync(0xffffffffu, acc, 1);
    acc += __shfl_xor_sync(0xffffffffu, acc, 2);
    if (!(tid & 3)) g_qadd[b * DD + n] = acc + b1[n] + b2[n];
  }
}

// ---------------------------------------------------------------------------
// Kernel 2: score GEMM — single fp16 term. Block: 128 rows resident,
// warp tile 32x64, W2 streamed cp.async 2-stage with 128-k stages.
// Epilogue also emits per-block (max, expsum) to g_msp.
// ---------------------------------------------------------------------------
#define A_STRIDE 1040          // (512+8) fp16 * 2 bytes
#define AH_OFF 0               // 128*1040 = 133120
#define BST_OFF 133120
#define B_RSTRIDE 272          // (128+8) fp16 * 2 bytes
#define B_STAGE 34816          // 128 rows * 272
#define Q_OFF 202752           // 133120 + 2*34816
#define V_OFF 204800
#define P_OFF 206848           // 256 floats + 16 scratch
#define SMEM_TOTAL 207936

__global__ void __launch_bounds__(256, 1) score_mma_kernel(
    const float* __restrict__ values, const float* __restrict__ Vv,
    const float* __restrict__ bv) {
  extern __shared__ char smem[];
  const uint32_t sb = smem_u32(smem);
  const int tid = threadIdx.x;
  const int wid = tid >> 5, lane = tid & 31;
  const int gid = lane >> 2, tig = lane & 3;
  const int wm = wid & 3, wn = wid >> 2;  // 4 m-warps x 2 n-warps
  const int m0 = blockIdx.x * 128;
  const int b = m0 >> 12;

  float* qsh = (float*)(smem + Q_OFF);
  float* vsh = (float*)(smem + V_OFF);
  float* part = (float*)(smem + P_OFF);
  float* red = part + 256;  // 16 floats scratch

  // ---- issue B stage0 for nc=0 first (overlaps A conversion) ----
  {
    uint32_t st = sb + BST_OFF;
#pragma unroll
    for (int i = 0; i < 8; i++) {
      int t2 = tid + i * 256;
      int r = t2 >> 4, q = t2 & 15;
      cp16(st + r * B_RSTRIDE + q * 16, g_w2f + (size_t)r * DD + q * 8);
    }
    CP_COMMIT();
  }

  // ---- A fill: 128 rows x 512 k -> fp16 plane ----
  for (int task = tid; task < 8192; task += 256) {
    int r = task >> 6, g = task & 63;
    const float4* p4 = (const float4*)(values + (size_t)(m0 + r) * DD + g * 8);
    float4 x0 = p4[0], x1 = p4[1];
    __half2 h0 = __floats2half2_rn(x0.x, x0.y);
    __half2 h1 = __floats2half2_rn(x0.z, x0.w);
    __half2 h2 = __floats2half2_rn(x1.x, x1.y);
    __half2 h3 = __floats2half2_rn(x1.z, x1.w);
    *(uint4*)(smem + AH_OFF + r * A_STRIDE + g * 16) =
        make_uint4(*(uint32_t*)&h0, *(uint32_t*)&h1, *(uint32_t*)&h2, *(uint32_t*)&h3);
  }
  for (int i = tid; i < DD; i += 256) {
    qsh[i] = g_qadd[b * DD + i];
    vsh[i] = Vv[i];
  }

  // ldmatrix per-lane addresses
  const int a_row = ((lane >> 3) & 1) * 8 + (lane & 7);
  const int a_col = (lane >> 4) * 16;
  const uint32_t aH_addr = sb + AH_OFF + (wm * 32 + a_row) * A_STRIDE + a_col;
  const int b_row = ((lane >> 4) & 1) * 8 + (lane & 7);
  const int b_col = ((lane >> 3) & 1) * 16;
  const uint32_t b_off = (wn * 64 + b_row) * B_RSTRIDE + b_col;

  float rowsum[4] = {0.f, 0.f, 0.f, 0.f};

  for (int nc = 0; nc < 4; ++nc) {
    float acc[2][8][4];
#pragma unroll
    for (int mi = 0; mi < 2; mi++)
#pragma unroll
      for (int ni = 0; ni < 8; ni++)
#pragma unroll
        for (int j = 0; j < 4; j++) acc[mi][ni][j] = 0.f;

    const unsigned short* Bg = g_w2f + (size_t)(nc * 128) * DD;

    for (int kt = 0; kt < 4; ++kt) {
      if (kt < 3) {
        uint32_t st = sb + BST_OFF + ((kt + 1) & 1) * B_STAGE;
        const unsigned short* Bk = Bg + (kt + 1) * 128;
#pragma unroll
        for (int i = 0; i < 8; i++) {
          int t2 = tid + i * 256;
          int r = t2 >> 4, q = t2 & 15;
          cp16(st + r * B_RSTRIDE + q * 16, Bk + (size_t)r * DD + q * 8);
        }
        CP_COMMIT();
        CP_WAIT1();
      } else {
        CP_WAIT0();
      }
      __syncthreads();  // stage kt ready (and A ready on first pass)

      const uint32_t stage = sb + BST_OFF + (kt & 1) * B_STAGE;
#pragma unroll
      for (int k16 = 0; k16 < 8; ++k16) {
        int kg = kt * 128 + k16 * 16;
        uint32_t aH[2][4], bH[4][4];
        ldsm_x4(aH[0], aH_addr + kg * 2);
        ldsm_x4(aH[1], aH_addr + 16 * A_STRIDE + kg * 2);
        uint32_t bbase = stage + b_off + k16 * 32;
        ldsm_x4(bH[0], bbase);
        ldsm_x4(bH[1], bbase + 16 * B_RSTRIDE);
        ldsm_x4(bH[2], bbase + 32 * B_RSTRIDE);
        ldsm_x4(bH[3], bbase + 48 * B_RSTRIDE);
#pragma unroll
        for (int mi = 0; mi < 2; mi++)
#pragma unroll
          for (int ni = 0; ni < 8; ni++)
            mma_f16(acc[mi][ni], aH[mi], &bH[ni >> 1][(ni & 1) * 2]);
      }
      __syncthreads();  // all readers done before stage is overwritten
    }

    // prefetch next nc's stage0 (both buffers free now)
    if (nc < 3) {
      uint32_t st = sb + BST_OFF;
      const unsigned short* Bn = g_w2f + (size_t)((nc + 1) * 128) * DD;
#pragma unroll
      for (int i = 0; i < 8; i++) {
        int t2 = tid + i * 256;
        int r = t2 >> 4, q = t2 & 15;
        cp16(st + r * B_RSTRIDE + q * 16, Bn + (size_t)r * DD + q * 8);
      }
      CP_COMMIT();
    }

    // epilogue for this 128-col chunk (tanh.approx: 1 MUFU per element)
#pragma unroll
    for (int mi = 0; mi < 2; mi++)
#pragma unroll
      for (int ni = 0; ni < 8; ni++)
#pragma unroll
        for (int j = 0; j < 4; j++) {
          int n = nc * 128 + wn * 64 + ni * 8 + tig * 2 + (j & 1);
          float h = tanh_fast(acc[mi][ni][j] + qsh[n]);
          rowsum[mi * 2 + (j >> 1)] = fmaf(h, vsh[n], rowsum[mi * 2 + (j >> 1)]);
        }
  }

#pragma unroll
  for (int i = 0; i < 4; i++) {
    rowsum[i] += __shfl_xor_sync(0xffffffffu, rowsum[i], 1);
    rowsum[i] += __shfl_xor_sync(0xffffffffu, rowsum[i], 2);
  }
  if (tig == 0) {
#pragma unroll
    for (int mi = 0; mi < 2; mi++)
#pragma unroll
      for (int ri = 0; ri < 2; ri++) {
        int row = wm * 32 + mi * 16 + ri * 8 + gid;
        part[wn * 128 + row] = rowsum[mi * 2 + ri];
      }
  }
  __syncthreads();
  float sval = -1e30f;
  if (tid < 128) {
    sval = part[tid] + part[128 + tid] + bv[0];
    g_scores[m0 + tid] = sval;
  }

  // ---- per-block (max, expsum) for softmax ----
  float mv = sval;
#pragma unroll
  for (int o = 16; o; o >>= 1) mv = fmaxf(mv, __shfl_xor_sync(0xffffffffu, mv, o));
  __syncthreads();  // part reads complete before red reuse
  if (lane == 0) red[wid] = mv;
  __syncthreads();
  float mloc = red[0];
#pragma unroll
  for (int i = 1; i < 8; i++) mloc = fmaxf(mloc, red[i]);
  float ev = (tid < 128) ? __expf(sval - mloc) : 0.f;
#pragma unroll
  for (int o = 16; o; o >>= 1) ev += __shfl_xor_sync(0xffffffffu, ev, o);
  __syncthreads();
  if (lane == 0) red[8 + wid] = ev;
  __syncthreads();
  if (tid == 0) {
    float v = 0.f;
#pragma unroll
    for (int i = 0; i < 8; i++) v += red[8 + i];
    g_msp[blockIdx.x * 2] = mloc;
    g_msp[blockIdx.x * 2 + 1] = v;
  }
}

// ---------------------------------------------------------------------------
// Kernel 4: context partials, attn written in-flight; inline softmax combine.
// Block = (s-chunk of 64, batch); 128 threads x float4 (coalesced 2KB/row).
// ---------------------------------------------------------------------------
#define SCH 64
__global__ void __launch_bounds__(128) ctx_partial_kernel(
    const float* __restrict__ values, float* __restrict__ out) {
  const int t = threadIdx.x;
  const int chunk = blockIdx.x;   // 0..63
  const int b = blockIdx.y;
  __shared__ float sM, sInv;
  __shared__ float ps[SS / SCH];

  // combine this batch's 32 (max, expsum) pairs
  if (t < 32) {
    float m = g_msp[(b * 32 + t) * 2];
    float sv = g_msp[(b * 32 + t) * 2 + 1];
    float M = m;
#pragma unroll
    for (int o = 16; o; o >>= 1) M = fmaxf(M, __shfl_xor_sync(0xffffffffu, M, o));
    float z = sv * __expf(m - M);
#pragma unroll
    for (int o = 16; o; o >>= 1) z += __shfl_xor_sync(0xffffffffu, z, o);
    if (t == 0) {
      sM = M;
      sInv = 1.0f / z;
    }
  }
  __syncthreads();
  const float m = sM, inv = sInv;

  const int s0 = chunk * (SS / SCH);
  const float* sc = g_scores + (size_t)b * SS + s0;
  float* attn = out + BB * DD + (size_t)b * SS + s0;
  const float4* vb = (const float4*)(values + ((size_t)b * SS + s0) * DD) + t;

  // probabilities for this chunk (64 values), shared by all threads
  if (t < SS / SCH) {
    float p = __expf(sc[t] - m) * inv;
    ps[t] = p;
    attn[t] = p;
  }
  __syncthreads();

  float4 acc = make_float4(0.f, 0.f, 0.f, 0.f);
#pragma unroll 8
  for (int s = 0; s < SS / SCH; s++) {
    float p = ps[s];
    float4 v = vb[(size_t)s * (DD / 4)];
    acc.x = fmaf(p, v.x, acc.x);
    acc.y = fmaf(p, v.y, acc.y);
    acc.z = fmaf(p, v.z, acc.z);
    acc.w = fmaf(p, v.w, acc.w);
  }
  *((float4*)(g_partial + ((size_t)(b * SCH + chunk)) * DD) + t) = acc;
}

// ---------------------------------------------------------------------------
// Kernel 5: final reduce — one block per batch, 512 threads; thread owns
// (d4 = t&127, quarter = t>>7 of 16 partials); quarters combined via SMEM in
// fixed order (deterministic across replays).
// ---------------------------------------------------------------------------
__global__ void __launch_bounds__(512) ctx_reduce_kernel(float* __restrict__ out) {
  const int b = blockIdx.x;
  const int t = threadIdx.x;
  const int d4 = t & 127;
  const int pq = t >> 7;  // 0..3
  __shared__ float4 sred[512];

  const float4* pp = (const float4*)(g_partial + (size_t)b * SCH * DD) + d4;
  float4 acc = make_float4(0.f, 0.f, 0.f, 0.f);
#pragma unroll 16
  for (int p = pq * 16; p < pq * 16 + 16; p++) {
    float4 v = pp[(size_t)p * (DD / 4)];
    acc.x += v.x;
    acc.y += v.y;
    acc.z += v.z;
    acc.w += v.w;
  }
  sred[t] = acc;
  __syncthreads();
  if (pq == 0) {
    float4 r0 = sred[d4];
    float4 r1 = sred[128 + d4];
    float4 r2 = sred[256 + d4];
    float4 r3 = sred[384 + d4];
    float4 r;
    r.x = ((r0.x + r1.x) + r2.x) + r3.x;
    r.y = ((r0.y + r1.y) + r2.y) + r3.y;
    r.z = ((r0.z + r1.z) + r2.z) + r3.z;
    r.w = ((r0.w + r1.w) + r2.w) + r3.w;
    *((float4*)out + b * (DD / 4) + d4) = r;
  }
}

// ---------------------------------------------------------------------------
extern "C" void kernel_launch(void* const* d_in, const int* in_sizes, int n_in,
                              void* d_out, int out_size) {
  const float* query = (const float*)d_in[0];
  const float* values = (const float*)d_in[1];
  const float* W1 = (const float*)d_in[2];
  const float* b1 = (const float*)d_in[3];
  const float* W2 = (const float*)d_in[4];
  const float* b2 = (const float*)d_in[5];
  const float* Vv = (const float*)d_in[6];
  const float* bv = (const float*)d_in[7];
  float* out = (float*)d_out;

  cudaFuncSetAttribute(score_mma_kernel,
                       cudaFuncAttributeMaxDynamicSharedMemorySize, SMEM_TOTAL);

  prep_kernel<<<384, 256>>>(W2, query, W1, b1, b2);
  score_mma_kernel<<<(BB * SS) / 128, 256, SMEM_TOTAL>>>(values, Vv, bv);
  ctx_partial_kernel<<<dim3(SCH, BB), 128>>>(values, out);
  ctx_reduce_kernel<<<BB, 512>>>(out);
}